// round 1
// baseline (speedup 1.0000x reference)
#include <cuda_runtime.h>
#include <math.h>
#include <stdint.h>

// ---------------- problem constants ----------------
#define BATCH   2
#define NQ      4096
#define NCTX    4096
#define DIMC    512
#define HEADS   8
#define DH      64
#define INNER   512          // HEADS*DH
#define MK      4097         // keys incl. null
#define SQSCALE 0.35355339059327373f   // sqrt(64^-0.5)

// ---------------- scratch (device globals: no allocation allowed) -----------
__device__ float g_xn[(size_t)BATCH * NQ * DIMC];          // layernormed x
__device__ float g_q [(size_t)BATCH * HEADS * NQ * DH];    // (b,h,n,d)
__device__ float g_k [(size_t)BATCH * HEADS * MK * DH];    // (b,h,mk,d)
__device__ float g_v [(size_t)BATCH * HEADS * MK * DH];
__device__ float g_ao[(size_t)BATCH * NQ * INNER];         // attention out (b,n,h*d)
__device__ float g_pj[(size_t)BATCH * NQ * DIMC];          // out proj result

// ---------------- layernorm: one row (512) per block, 128 threads -----------
// WHICH==0: in = param x,  out = g_xn
// WHICH==1: in = g_pj,     out = param out
template <int WHICH>
__global__ void __launch_bounds__(128) ln_kernel(const float* __restrict__ inp,
                                                 const float* __restrict__ g,
                                                 float* __restrict__ outp)
{
    const float* in  = (WHICH == 0) ? inp  : g_pj;
    float*       out = (WHICH == 0) ? g_xn : outp;

    int row = blockIdx.x;
    int tid = threadIdx.x;
    const float* rptr = in + (size_t)row * DIMC;

    float4 v = reinterpret_cast<const float4*>(rptr)[tid];
    float s  = v.x + v.y + v.z + v.w;
    float ss = v.x * v.x + v.y * v.y + v.z * v.z + v.w * v.w;

    #pragma unroll
    for (int o = 16; o > 0; o >>= 1) {
        s  += __shfl_down_sync(0xffffffffu, s,  o);
        ss += __shfl_down_sync(0xffffffffu, ss, o);
    }
    __shared__ float sb[8];
    int wid  = tid >> 5;
    int lane = tid & 31;
    if (lane == 0) { sb[wid] = s; sb[4 + wid] = ss; }
    __syncthreads();
    float S  = sb[0] + sb[1] + sb[2] + sb[3];
    float SS = sb[4] + sb[5] + sb[6] + sb[7];

    float mean = S * (1.0f / DIMC);
    float var  = SS * (1.0f / DIMC) - mean * mean;
    float rstd = rsqrtf(var + 1e-5f);

    float4 gv = reinterpret_cast<const float4*>(g)[tid];
    float4 o4;
    o4.x = (v.x - mean) * rstd * gv.x;
    o4.y = (v.y - mean) * rstd * gv.y;
    o4.z = (v.z - mean) * rstd * gv.z;
    o4.w = (v.w - mean) * rstd * gv.w;
    reinterpret_cast<float4*>(out + (size_t)row * DIMC)[tid] = o4;
}

// ---------------- null kv fill ----------------------------------------------
__global__ void null_fill_kernel(const float* __restrict__ null_kv)
{
    int bh = blockIdx.x;     // 0..15
    int d  = threadIdx.x;    // 0..63
    g_k[(size_t)bh * MK * DH + d] = null_kv[d] * SQSCALE;
    g_v[(size_t)bh * MK * DH + d] = null_kv[DH + d];
}

// ---------------- tiled fp32 GEMM: C(8192 x NC) = A(8192x512) @ B(512xNC) ---
// 64x64 tile, 256 threads, 4x4 per thread.
// MODE 0: A = g_xn,  epilogue -> g_q (scaled, (b,h,n,d) layout)
// MODE 1: A = Aext (context), epilogue -> g_k (scaled) / g_v, row+1 offset
// MODE 2: A = g_ao, epilogue -> g_pj plain
template <int MODE, int NC>
__global__ void __launch_bounds__(256) proj_kernel(const float* __restrict__ Bm,
                                                   const float* __restrict__ Aext)
{
    const float* A = (MODE == 0) ? g_xn : (MODE == 1 ? Aext : g_ao);

    __shared__ float As[16 * 68];
    __shared__ float Bs[16 * 68];

    int tid = threadIdx.x;
    int tx = tid & 15, ty = tid >> 4;
    int row0 = blockIdx.y * 64;
    int col0 = blockIdx.x * 64;

    float acc[4][4] = {};

    for (int k0 = 0; k0 < 512; k0 += 16) {
        #pragma unroll
        for (int p = 0; p < 4; p++) {
            int idx = tid + p * 256;
            int r = idx >> 4, kk = idx & 15;
            As[kk * 68 + r] = A[(size_t)(row0 + r) * 512 + k0 + kk];
        }
        #pragma unroll
        for (int p = 0; p < 4; p++) {
            int idx = tid + p * 256;
            int kk = idx >> 6, c = idx & 63;
            Bs[kk * 68 + c] = Bm[(size_t)(k0 + kk) * NC + col0 + c];
        }
        __syncthreads();
        #pragma unroll
        for (int kk = 0; kk < 16; kk++) {
            float a[4], b[4];
            #pragma unroll
            for (int i = 0; i < 4; i++) a[i] = As[kk * 68 + ty * 4 + i];
            #pragma unroll
            for (int j = 0; j < 4; j++) b[j] = Bs[kk * 68 + tx * 4 + j];
            #pragma unroll
            for (int i = 0; i < 4; i++)
                #pragma unroll
                for (int j = 0; j < 4; j++)
                    acc[i][j] += a[i] * b[j];
        }
        __syncthreads();
    }

    #pragma unroll
    for (int i = 0; i < 4; i++) {
        int row = row0 + ty * 4 + i;
        #pragma unroll
        for (int j = 0; j < 4; j++) {
            int col = col0 + tx * 4 + j;
            float val = acc[i][j];
            if (MODE == 0) {
                int b = row >> 12, n = row & 4095;
                int h = col >> 6,  dd = col & 63;
                g_q[(((size_t)(b * HEADS + h)) * NQ + n) * DH + dd] = val * SQSCALE;
            } else if (MODE == 1) {
                int b = row >> 12, mr = row & 4095;
                if (col < 512) {
                    int h = col >> 6, dd = col & 63;
                    g_k[(((size_t)(b * HEADS + h)) * MK + mr + 1) * DH + dd] = val * SQSCALE;
                } else {
                    int c2 = col - 512;
                    int h = c2 >> 6, dd = c2 & 63;
                    g_v[(((size_t)(b * HEADS + h)) * MK + mr + 1) * DH + dd] = val;
                }
            } else {
                g_pj[(size_t)row * 512 + col] = val;
            }
        }
    }
}

// ---------------- flash attention: 64 queries x 64-key chunks ----------------
#define SP 68   // smem pitch (floats)
__global__ void __launch_bounds__(256) attn_kernel(const int* __restrict__ mask)
{
    extern __shared__ float sm[];
    float* Qs = sm;
    float* Ks = sm + 64 * SP;
    float* Vs = sm + 2 * 64 * SP;
    float* Ss = sm + 3 * 64 * SP;
    float* row_m  = sm + 4 * 64 * SP;
    float* row_l  = row_m + 64;
    float* row_sc = row_l + 64;
    float* msk    = row_sc + 64;

    int tid = threadIdx.x;
    int tx = tid & 15, ty = tid >> 4;
    int bh = blockIdx.y;
    int b = bh >> 3, h = bh & 7;
    int n0 = blockIdx.x << 6;

    const float* qp    = g_q + ((size_t)bh * NQ + n0) * DH;
    const float* kbase = g_k + (size_t)bh * MK * DH;
    const float* vbase = g_v + (size_t)bh * MK * DH;

    // load Q tile (64x64)
    #pragma unroll
    for (int p = 0; p < 4; p++) {
        int f = tid + p * 256;
        int r = f >> 4, s4 = (f & 15) << 2;
        float4 q4 = *reinterpret_cast<const float4*>(qp + (size_t)r * DH + s4);
        *reinterpret_cast<float4*>(Qs + r * SP + s4) = q4;
    }
    if (tid < 64) { row_m[tid] = -1e30f; row_l[tid] = 0.0f; }

    float acc[4][4] = {};
    __syncthreads();

    for (int c0 = 0; c0 < MK; c0 += 64) {
        // load K, V chunk (guarded, zero-fill past MK)
        #pragma unroll
        for (int p = 0; p < 4; p++) {
            int f = tid + p * 256;
            int r = f >> 4, s4 = (f & 15) << 2;
            int j = c0 + r;
            float4 k4 = make_float4(0.f, 0.f, 0.f, 0.f);
            float4 v4 = k4;
            if (j < MK) {
                k4 = *reinterpret_cast<const float4*>(kbase + (size_t)j * DH + s4);
                v4 = *reinterpret_cast<const float4*>(vbase + (size_t)j * DH + s4);
            }
            *reinterpret_cast<float4*>(Ks + r * SP + s4) = k4;
            *reinterpret_cast<float4*>(Vs + r * SP + s4) = v4;
        }
        if (tid < 64) {
            int j = c0 + tid;
            float ok;
            if (j == 0)       ok = 1.0f;
            else if (j < MK)  ok = mask[b * NCTX + (j - 1)] ? 1.0f : 0.0f;
            else              ok = 0.0f;
            msk[tid] = ok;
        }
        __syncthreads();

        // S = Q @ K^T  (4x4 per thread), vectorized along k
        float sa[4][4] = {};
        #pragma unroll 4
        for (int kk = 0; kk < 64; kk += 4) {
            float4 a4[4], b4[4];
            #pragma unroll
            for (int i = 0; i < 4; i++)
                a4[i] = *reinterpret_cast<const float4*>(Qs + (ty * 4 + i) * SP + kk);
            #pragma unroll
            for (int j = 0; j < 4; j++)
                b4[j] = *reinterpret_cast<const float4*>(Ks + (tx * 4 + j) * SP + kk);
            #pragma unroll
            for (int i = 0; i < 4; i++)
                #pragma unroll
                for (int j = 0; j < 4; j++) {
                    sa[i][j] += a4[i].x * b4[j].x;
                    sa[i][j] += a4[i].y * b4[j].y;
                    sa[i][j] += a4[i].z * b4[j].z;
                    sa[i][j] += a4[i].w * b4[j].w;
                }
        }
        // masked store to Ss
        #pragma unroll
        for (int i = 0; i < 4; i++)
            #pragma unroll
            for (int j = 0; j < 4; j++) {
                int cc = tx * 4 + j;
                Ss[(ty * 4 + i) * SP + cc] = (msk[cc] > 0.0f) ? sa[i][j] : -1e30f;
            }
        __syncthreads();

        // online softmax stats: 4 threads per row
        {
            int rr = tid >> 2, q4 = tid & 3;
            int base = rr * SP + q4 * 16;
            float sv[16];
            float mx = -1e30f;
            #pragma unroll
            for (int u = 0; u < 16; u++) { sv[u] = Ss[base + u]; mx = fmaxf(mx, sv[u]); }
            mx = fmaxf(mx, __shfl_xor_sync(0xffffffffu, mx, 1));
            mx = fmaxf(mx, __shfl_xor_sync(0xffffffffu, mx, 2));
            float mold = row_m[rr];
            float mnew = fmaxf(mold, mx);
            float sum = 0.0f;
            #pragma unroll
            for (int u = 0; u < 16; u++) {
                float pv = __expf(sv[u] - mnew);
                Ss[base + u] = pv;
                sum += pv;
            }
            sum += __shfl_xor_sync(0xffffffffu, sum, 1);
            sum += __shfl_xor_sync(0xffffffffu, sum, 2);
            if (q4 == 0) {
                float fsc = __expf(mold - mnew);
                row_sc[rr] = fsc;
                row_m[rr]  = mnew;
                row_l[rr]  = row_l[rr] * fsc + sum;
            }
        }
        __syncthreads();

        // rescale accumulator
        #pragma unroll
        for (int i = 0; i < 4; i++) {
            float fsc = row_sc[ty * 4 + i];
            #pragma unroll
            for (int j = 0; j < 4; j++) acc[i][j] *= fsc;
        }

        // O += P @ V, vectorized along j (key) dim
        #pragma unroll 4
        for (int jj = 0; jj < 64; jj += 4) {
            float4 p4[4];
            #pragma unroll
            for (int i = 0; i < 4; i++)
                p4[i] = *reinterpret_cast<const float4*>(Ss + (ty * 4 + i) * SP + jj);
            float4 v0 = *reinterpret_cast<const float4*>(Vs + (jj + 0) * SP + tx * 4);
            float4 v1 = *reinterpret_cast<const float4*>(Vs + (jj + 1) * SP + tx * 4);
            float4 v2 = *reinterpret_cast<const float4*>(Vs + (jj + 2) * SP + tx * 4);
            float4 v3 = *reinterpret_cast<const float4*>(Vs + (jj + 3) * SP + tx * 4);
            #pragma unroll
            for (int i = 0; i < 4; i++) {
                acc[i][0] += p4[i].x * v0.x + p4[i].y * v1.x + p4[i].z * v2.x + p4[i].w * v3.x;
                acc[i][1] += p4[i].x * v0.y + p4[i].y * v1.y + p4[i].z * v2.y + p4[i].w * v3.y;
                acc[i][2] += p4[i].x * v0.z + p4[i].y * v1.z + p4[i].z * v2.z + p4[i].w * v3.z;
                acc[i][3] += p4[i].x * v0.w + p4[i].y * v1.w + p4[i].z * v2.w + p4[i].w * v3.w;
            }
        }
        __syncthreads();
    }

    // final normalize + scatter to (b, n, h*64+d)
    #pragma unroll
    for (int i = 0; i < 4; i++) {
        int r = ty * 4 + i;
        float inv = 1.0f / row_l[r];
        #pragma unroll
        for (int j = 0; j < 4; j++) {
            int c = tx * 4 + j;
            g_ao[((size_t)(b * NQ) + (n0 + r)) * INNER + h * DH + c] = acc[i][j] * inv;
        }
    }
}

// ---------------- launch ------------------------------------------------------
extern "C" void kernel_launch(void* const* d_in, const int* in_sizes, int n_in,
                              void* d_out, int out_size)
{
    const float* x       = (const float*)d_in[0];
    const float* context = (const float*)d_in[1];
    const int*   mask    = (const int*)  d_in[2];   // bool promoted; !=0 works for int32 or f32 bits
    const float* g_x     = (const float*)d_in[3];
    const float* null_kv = (const float*)d_in[4];
    const float* Wq      = (const float*)d_in[5];
    const float* Wkv     = (const float*)d_in[6];
    const float* Wo      = (const float*)d_in[7];
    const float* g_outp  = (const float*)d_in[8];
    float* out = (float*)d_out;

    (void)in_sizes; (void)n_in; (void)out_size;

    // 1) layernorm(x) -> g_xn
    ln_kernel<0><<<BATCH * NQ, 128>>>(x, g_x, nullptr);

    // 2) Q projection (scaled, scattered to (b,h,n,d))
    proj_kernel<0, 512><<<dim3(8, 128), 256>>>(Wq, nullptr);

    // 3) KV projection (k scaled, rows offset by 1 for null slot)
    proj_kernel<1, 1024><<<dim3(16, 128), 256>>>(Wkv, context);

    // 4) null kv row
    null_fill_kernel<<<BATCH * HEADS, DH>>>(null_kv);

    // 5) flash attention
    static const size_t attn_smem = (4 * 64 * SP + 4 * 64) * sizeof(float);
    cudaFuncSetAttribute(attn_kernel, cudaFuncAttributeMaxDynamicSharedMemorySize,
                         (int)attn_smem);
    attn_kernel<<<dim3(NQ / 64, BATCH * HEADS), 256, attn_smem>>>(mask);

    // 6) output projection
    proj_kernel<2, 512><<<dim3(8, 128), 256>>>(Wo, nullptr);

    // 7) final layernorm -> d_out
    ln_kernel<1><<<BATCH * NQ, 128>>>(nullptr, g_outp, out);
}

// round 3
// speedup vs baseline: 2.3312x; 2.3312x over previous
#include <cuda_runtime.h>
#include <cuda_bf16.h>
#include <math.h>
#include <stdint.h>

// ---------------- problem constants ----------------
#define BATCH   2
#define NQ      4096
#define NCTX    4096
#define DIMC    512
#define HEADS   8
#define DH      64
#define INNER   512
#define MK      4097         // keys incl. null
#define MKP     4104         // padded stride for V^T (16B-aligned rows)
#define SQSCALE 0.35355339059327373f   // sqrt(64^-0.5)

// ---------------- scratch ----------------------------------------------------
__device__ float g_xn[(size_t)BATCH * NQ * DIMC];
__device__ float g_ao[(size_t)BATCH * NQ * INNER];
__device__ float g_pj[(size_t)BATCH * NQ * DIMC];

__device__ __nv_bfloat16 g_qh[(size_t)BATCH * HEADS * NQ * DH];
__device__ __nv_bfloat16 g_ql[(size_t)BATCH * HEADS * NQ * DH];
__device__ __nv_bfloat16 g_kh[(size_t)BATCH * HEADS * MK * DH];
__device__ __nv_bfloat16 g_kl[(size_t)BATCH * HEADS * MK * DH];
__device__ __nv_bfloat16 g_vth[(size_t)BATCH * HEADS * DH * MKP];  // [bh][d][key]
__device__ __nv_bfloat16 g_vtl[(size_t)BATCH * HEADS * DH * MKP];

// ---------------- helpers -----------------------------------------------------
__device__ __forceinline__ void bsplit(float v, __nv_bfloat16* hi, __nv_bfloat16* lo) {
    __nv_bfloat16 h = __float2bfloat16(v);
    *hi = h;
    *lo = __float2bfloat16(v - __bfloat162float(h));
}
__device__ __forceinline__ uint32_t pack_bf16x2(float lo_elem, float hi_elem) {
    uint32_t r;
    asm("cvt.rn.bf16x2.f32 %0, %1, %2;" : "=r"(r) : "f"(hi_elem), "f"(lo_elem));
    return r;
}
// D(16x8,f32) += A(16x16,bf16) * B(16x8,bf16)
__device__ __forceinline__ void mma16816(float* d, const uint32_t* a, uint32_t b0, uint32_t b1) {
    asm volatile("mma.sync.aligned.m16n8k16.row.col.f32.bf16.bf16.f32 "
        "{%0,%1,%2,%3}, {%4,%5,%6,%7}, {%8,%9}, {%0,%1,%2,%3};"
        : "+f"(d[0]), "+f"(d[1]), "+f"(d[2]), "+f"(d[3])
        : "r"(a[0]), "r"(a[1]), "r"(a[2]), "r"(a[3]), "r"(b0), "r"(b1));
}

// ---------------- layernorm --------------------------------------------------
template <int WHICH>
__global__ void __launch_bounds__(128) ln_kernel(const float* __restrict__ inp,
                                                 const float* __restrict__ g,
                                                 float* __restrict__ outp)
{
    const float* in  = (WHICH == 0) ? inp  : g_pj;
    float*       out = (WHICH == 0) ? g_xn : outp;
    int row = blockIdx.x;
    int tid = threadIdx.x;
    const float* rptr = in + (size_t)row * DIMC;

    float4 v = reinterpret_cast<const float4*>(rptr)[tid];
    float s  = v.x + v.y + v.z + v.w;
    float ss = v.x * v.x + v.y * v.y + v.z * v.z + v.w * v.w;
    #pragma unroll
    for (int o = 16; o > 0; o >>= 1) {
        s  += __shfl_down_sync(0xffffffffu, s,  o);
        ss += __shfl_down_sync(0xffffffffu, ss, o);
    }
    __shared__ float sb[8];
    int wid = tid >> 5, lane = tid & 31;
    if (lane == 0) { sb[wid] = s; sb[4 + wid] = ss; }
    __syncthreads();
    float S  = sb[0] + sb[1] + sb[2] + sb[3];
    float SS = sb[4] + sb[5] + sb[6] + sb[7];
    float mean = S * (1.0f / DIMC);
    float var  = SS * (1.0f / DIMC) - mean * mean;
    float rstd = rsqrtf(var + 1e-5f);
    float4 gv = reinterpret_cast<const float4*>(g)[tid];
    float4 o4;
    o4.x = (v.x - mean) * rstd * gv.x;
    o4.y = (v.y - mean) * rstd * gv.y;
    o4.z = (v.z - mean) * rstd * gv.z;
    o4.w = (v.w - mean) * rstd * gv.w;
    reinterpret_cast<float4*>(out + (size_t)row * DIMC)[tid] = o4;
}

// ---------------- null kv fill -----------------------------------------------
__global__ void null_fill_kernel(const float* __restrict__ null_kv)
{
    int bh = blockIdx.x;
    int d  = threadIdx.x;
    size_t kidx = (size_t)bh * MK * DH + d;
    bsplit(null_kv[d] * SQSCALE, &g_kh[kidx], &g_kl[kidx]);
    size_t vidx = ((size_t)bh * DH + d) * MKP + 0;
    bsplit(null_kv[DH + d], &g_vth[vidx], &g_vtl[vidx]);
}

// ---------------- projection GEMM (fp32 SIMT) --------------------------------
template <int MODE, int NC>
__global__ void __launch_bounds__(256) proj_kernel(const float* __restrict__ Bm,
                                                   const float* __restrict__ Aext)
{
    const float* A = (MODE == 0) ? g_xn : (MODE == 1 ? Aext : g_ao);

    __shared__ float As[16 * 68];
    __shared__ float Bs[16 * 68];

    int tid = threadIdx.x;
    int tx = tid & 15, ty = tid >> 4;
    int row0 = blockIdx.y * 64;
    int col0 = blockIdx.x * 64;

    float acc[4][4] = {};
    for (int k0 = 0; k0 < 512; k0 += 16) {
        #pragma unroll
        for (int p = 0; p < 4; p++) {
            int idx = tid + p * 256;
            int r = idx >> 4, kk = idx & 15;
            As[kk * 68 + r] = A[(size_t)(row0 + r) * 512 + k0 + kk];
        }
        #pragma unroll
        for (int p = 0; p < 4; p++) {
            int idx = tid + p * 256;
            int kk = idx >> 6, c = idx & 63;
            Bs[kk * 68 + c] = Bm[(size_t)(k0 + kk) * NC + col0 + c];
        }
        __syncthreads();
        #pragma unroll
        for (int kk = 0; kk < 16; kk++) {
            float a[4], b[4];
            #pragma unroll
            for (int i = 0; i < 4; i++) a[i] = As[kk * 68 + ty * 4 + i];
            #pragma unroll
            for (int j = 0; j < 4; j++) b[j] = Bs[kk * 68 + tx * 4 + j];
            #pragma unroll
            for (int i = 0; i < 4; i++)
                #pragma unroll
                for (int j = 0; j < 4; j++)
                    acc[i][j] += a[i] * b[j];
        }
        __syncthreads();
    }

    #pragma unroll
    for (int i = 0; i < 4; i++) {
        int row = row0 + ty * 4 + i;
        #pragma unroll
        for (int j = 0; j < 4; j++) {
            int col = col0 + tx * 4 + j;
            float val = acc[i][j];
            if (MODE == 0) {
                int b = row >> 12, n = row & 4095;
                int h = col >> 6,  dd = col & 63;
                size_t idx = (((size_t)(b * HEADS + h)) * NQ + n) * DH + dd;
                bsplit(val * SQSCALE, &g_qh[idx], &g_ql[idx]);
            } else if (MODE == 1) {
                int b = row >> 12, mr = row & 4095;
                if (col < 512) {
                    int h = col >> 6, dd = col & 63;
                    size_t idx = (((size_t)(b * HEADS + h)) * MK + mr + 1) * DH + dd;
                    bsplit(val * SQSCALE, &g_kh[idx], &g_kl[idx]);
                } else {
                    int c2 = col - 512;
                    int h = c2 >> 6, dd = c2 & 63;
                    size_t idx = (((size_t)(b * HEADS + h)) * DH + dd) * MKP + (mr + 1);
                    bsplit(val, &g_vth[idx], &g_vtl[idx]);
                }
            } else {
                g_pj[(size_t)row * 512 + col] = val;
            }
        }
    }
}

// ---------------- FA2-style attention with mma.sync (bf16 split-3) -----------
// CTA: 64 queries x one (b,h). 4 warps x 16 rows. Key chunks of 64.
// Smem pitch: 72 bf16 = 144B -> conflict-free fragment reads.
#define SPIT 72

__global__ void __launch_bounds__(128) attn_mma_kernel(const int* __restrict__ mask)
{
    __shared__ __align__(16) __nv_bfloat16 sKh[64 * SPIT];
    __shared__ __align__(16) __nv_bfloat16 sKl[64 * SPIT];
    __shared__ __align__(16) __nv_bfloat16 sVh[64 * SPIT];   // V^T [dim][key]
    __shared__ __align__(16) __nv_bfloat16 sVl[64 * SPIT];
    __shared__ float msks[64];

    int tid  = threadIdx.x;
    int wid  = tid >> 5;
    int lane = tid & 31;
    int g    = lane >> 2;          // row group 0..7
    int qoff = (lane & 3) << 1;    // col pair 0,2,4,6
    int bh = blockIdx.y;
    int b = bh >> 3, h = bh & 7;
    int n0 = blockIdx.x << 6;

    // ---- load Q fragments (rows n0 + wid*16 + g/g+8), hi & lo ----
    uint32_t qfh[4][4], qfl[4][4];
    {
        const __nv_bfloat16* q0h = g_qh + ((size_t)bh * NQ + n0 + wid * 16 + g) * DH;
        const __nv_bfloat16* q0l = g_ql + ((size_t)bh * NQ + n0 + wid * 16 + g) * DH;
        #pragma unroll
        for (int kt = 0; kt < 4; kt++) {
            int d0 = kt * 16 + qoff;
            qfh[kt][0] = *(const uint32_t*)(q0h + d0);
            qfh[kt][1] = *(const uint32_t*)(q0h + 8 * DH + d0);
            qfh[kt][2] = *(const uint32_t*)(q0h + d0 + 8);
            qfh[kt][3] = *(const uint32_t*)(q0h + 8 * DH + d0 + 8);
            qfl[kt][0] = *(const uint32_t*)(q0l + d0);
            qfl[kt][1] = *(const uint32_t*)(q0l + 8 * DH + d0);
            qfl[kt][2] = *(const uint32_t*)(q0l + d0 + 8);
            qfl[kt][3] = *(const uint32_t*)(q0l + 8 * DH + d0 + 8);
        }
    }

    float oacc[8][4] = {};
    float sum0 = 0.0f, sum1 = 0.0f;

    for (int c0 = 0; c0 < MK; c0 += 64) {
        __syncthreads();   // protect smem reuse

        // ---- stage K rows / V^T rows (one array per warp) ----
        if (wid < 2) {
            const __nv_bfloat16* gk = (wid == 0) ? g_kh : g_kl;
            __nv_bfloat16* sK = (wid == 0) ? sKh : sKl;
            #pragma unroll
            for (int i = 0; i < 2; i++) {
                int r = (lane << 1) | i;
                uint4* dst = (uint4*)(sK + r * SPIT);
                int j = c0 + r;
                if (j < MK) {
                    const uint4* src = (const uint4*)(gk + ((size_t)bh * MK + j) * DH);
                    #pragma unroll
                    for (int w = 0; w < 8; w++) dst[w] = src[w];
                } else {
                    uint4 z = {0u, 0u, 0u, 0u};
                    #pragma unroll
                    for (int w = 0; w < 8; w++) dst[w] = z;
                }
            }
        } else {
            const __nv_bfloat16* gv = (wid == 2) ? g_vth : g_vtl;
            __nv_bfloat16* sV = (wid == 2) ? sVh : sVl;
            #pragma unroll
            for (int i = 0; i < 2; i++) {
                int dd = (lane << 1) | i;
                const __nv_bfloat16* src = gv + ((size_t)bh * DH + dd) * MKP + c0;
                if (c0 + 64 <= MK) {
                    uint4* dst = (uint4*)(sV + dd * SPIT);
                    #pragma unroll
                    for (int w = 0; w < 8; w++) dst[w] = ((const uint4*)src)[w];
                } else {
                    __nv_bfloat16* db = sV + dd * SPIT;
                    for (int e = 0; e < 64; e++)
                        db[e] = (c0 + e < MK) ? src[e] : __float2bfloat16(0.0f);
                }
            }
        }
        if (tid < 64) {
            int j = c0 + tid;
            float ok;
            if (j == 0)      ok = 1.0f;
            else if (j < MK) ok = mask[b * NCTX + (j - 1)] ? 1.0f : 0.0f;
            else             ok = 0.0f;
            msks[tid] = ok;
        }
        __syncthreads();

        // ---- S = Q K^T (3 split terms) ----
        float sacc[8][4] = {};
        #pragma unroll
        for (int term = 0; term < 3; term++) {
            const uint32_t (*qa)[4] = (term == 2) ? qfl : qfh;
            const char* kb = (const char*)((term == 1) ? sKl : sKh);
            #pragma unroll
            for (int kt = 0; kt < 4; kt++) {
                #pragma unroll
                for (int nt = 0; nt < 8; nt++) {
                    const char* bp = kb + (nt * 8 + g) * (SPIT * 2) + (kt * 16 + qoff) * 2;
                    uint32_t b0 = *(const uint32_t*)bp;
                    uint32_t b1 = *(const uint32_t*)(bp + 16);
                    mma16816(sacc[nt], qa[kt], b0, b1);
                }
            }
        }

        // ---- softmax (no max-subtract) + pack P fragments ----
        uint32_t pfh[4][4], pfl[4][4];
        #pragma unroll
        for (int nt = 0; nt < 8; nt++) {
            float2 mv = *(const float2*)(msks + nt * 8 + qoff);
            float p0 = mv.x * __expf(fminf(sacc[nt][0], 30.0f));
            float p1 = mv.y * __expf(fminf(sacc[nt][1], 30.0f));
            float p2 = mv.x * __expf(fminf(sacc[nt][2], 30.0f));
            float p3 = mv.y * __expf(fminf(sacc[nt][3], 30.0f));
            sum0 += p0 + p1;
            sum1 += p2 + p3;
            float h0 = __bfloat162float(__float2bfloat16(p0));
            float h1 = __bfloat162float(__float2bfloat16(p1));
            float h2 = __bfloat162float(__float2bfloat16(p2));
            float h3 = __bfloat162float(__float2bfloat16(p3));
            int kt = nt >> 1, hf = (nt & 1) << 1;
            pfh[kt][hf + 0] = pack_bf16x2(h0, h1);
            pfh[kt][hf + 1] = pack_bf16x2(h2, h3);
            pfl[kt][hf + 0] = pack_bf16x2(p0 - h0, p1 - h1);
            pfl[kt][hf + 1] = pack_bf16x2(p2 - h2, p3 - h3);
        }

        // ---- O += P V (3 split terms) ----
        #pragma unroll
        for (int term = 0; term < 3; term++) {
            const uint32_t (*pa)[4] = (term == 2) ? pfl : pfh;
            const char* vb = (const char*)((term == 1) ? sVl : sVh);
            #pragma unroll
            for (int kt = 0; kt < 4; kt++) {
                #pragma unroll
                for (int nt = 0; nt < 8; nt++) {
                    const char* bp = vb + (nt * 8 + g) * (SPIT * 2) + (kt * 16 + qoff) * 2;
                    uint32_t b0 = *(const uint32_t*)bp;
                    uint32_t b1 = *(const uint32_t*)(bp + 16);
                    mma16816(oacc[nt], pa[kt], b0, b1);
                }
            }
        }
    }

    // ---- reduce row sums across quad lanes, normalize, store ----
    sum0 += __shfl_xor_sync(0xffffffffu, sum0, 1);
    sum0 += __shfl_xor_sync(0xffffffffu, sum0, 2);
    sum1 += __shfl_xor_sync(0xffffffffu, sum1, 1);
    sum1 += __shfl_xor_sync(0xffffffffu, sum1, 2);
    float inv0 = 1.0f / sum0;
    float inv1 = 1.0f / sum1;

    float* orow0 = g_ao + ((size_t)b * NQ + n0 + wid * 16 + g) * INNER + h * DH;
    float* orow1 = orow0 + 8 * INNER;
    #pragma unroll
    for (int nt = 0; nt < 8; nt++) {
        float2 v0 = make_float2(oacc[nt][0] * inv0, oacc[nt][1] * inv0);
        float2 v1 = make_float2(oacc[nt][2] * inv1, oacc[nt][3] * inv1);
        *(float2*)(orow0 + nt * 8 + qoff) = v0;
        *(float2*)(orow1 + nt * 8 + qoff) = v1;
    }
}

// ---------------- launch ------------------------------------------------------
extern "C" void kernel_launch(void* const* d_in, const int* in_sizes, int n_in,
                              void* d_out, int out_size)
{
    const float* x       = (const float*)d_in[0];
    const float* context = (const float*)d_in[1];
    const int*   mask    = (const int*)  d_in[2];
    const float* g_x     = (const float*)d_in[3];
    const float* null_kv = (const float*)d_in[4];
    const float* Wq      = (const float*)d_in[5];
    const float* Wkv     = (const float*)d_in[6];
    const float* Wo      = (const float*)d_in[7];
    const float* g_outp  = (const float*)d_in[8];
    float* out = (float*)d_out;
    (void)in_sizes; (void)n_in; (void)out_size;

    ln_kernel<0><<<BATCH * NQ, 128>>>(x, g_x, nullptr);
    proj_kernel<0, 512><<<dim3(8, 128), 256>>>(Wq, nullptr);
    proj_kernel<1, 1024><<<dim3(16, 128), 256>>>(Wkv, context);
    null_fill_kernel<<<BATCH * HEADS, DH>>>(null_kv);

    attn_mma_kernel<<<dim3(NQ / 64, BATCH * HEADS), 128>>>(mask);

    proj_kernel<2, 512><<<dim3(8, 128), 256>>>(Wo, nullptr);
    ln_kernel<1><<<BATCH * NQ, 128>>>(nullptr, g_outp, out);
}

// round 4
// speedup vs baseline: 2.8518x; 1.2233x over previous
#include <cuda_runtime.h>
#include <cuda_bf16.h>
#include <math.h>
#include <stdint.h>

// ---------------- problem constants ----------------
#define BATCH   2
#define NQ      4096
#define NCTX    4096
#define DIMC    512
#define HEADS   8
#define DH      64
#define INNER   512
#define MK      4097         // keys incl. null
#define MKP     4104         // padded stride for V^T (16B-aligned rows)
#define SQSCALE 0.35355339059327373f   // sqrt(64^-0.5)

// ---------------- scratch ----------------------------------------------------
__device__ float g_xn[(size_t)BATCH * NQ * DIMC];
__device__ float g_ao[(size_t)BATCH * NQ * INNER];
__device__ float g_pj[(size_t)BATCH * NQ * DIMC];

__device__ __nv_bfloat16 g_qh[(size_t)BATCH * HEADS * NQ * DH];
__device__ __nv_bfloat16 g_ql[(size_t)BATCH * HEADS * NQ * DH];
__device__ __nv_bfloat16 g_kh[(size_t)BATCH * HEADS * MK * DH];
__device__ __nv_bfloat16 g_kl[(size_t)BATCH * HEADS * MK * DH];
__device__ __nv_bfloat16 g_vth[(size_t)BATCH * HEADS * DH * MKP];  // [bh][d][key]
__device__ __nv_bfloat16 g_vtl[(size_t)BATCH * HEADS * DH * MKP];

// transposed/split weights: Wt[n][k], k = 512
__device__ __nv_bfloat16 g_wqh[512 * 512],  g_wql[512 * 512];
__device__ __nv_bfloat16 g_wkvh[1024 * 512], g_wkvl[1024 * 512];
__device__ __nv_bfloat16 g_woh[512 * 512],  g_wol[512 * 512];

// ---------------- helpers -----------------------------------------------------
__device__ __forceinline__ void bsplit(float v, __nv_bfloat16* hi, __nv_bfloat16* lo) {
    __nv_bfloat16 h = __float2bfloat16(v);
    *hi = h;
    *lo = __float2bfloat16(v - __bfloat162float(h));
}
__device__ __forceinline__ uint32_t pack_bf16x2(float lo_elem, float hi_elem) {
    uint32_t r;
    asm("cvt.rn.bf16x2.f32 %0, %1, %2;" : "=r"(r) : "f"(hi_elem), "f"(lo_elem));
    return r;
}
// D(16x8,f32) += A(16x16,bf16) * B(16x8,bf16)
__device__ __forceinline__ void mma16816(float* d, const uint32_t* a, uint32_t b0, uint32_t b1) {
    asm volatile("mma.sync.aligned.m16n8k16.row.col.f32.bf16.bf16.f32 "
        "{%0,%1,%2,%3}, {%4,%5,%6,%7}, {%8,%9}, {%0,%1,%2,%3};"
        : "+f"(d[0]), "+f"(d[1]), "+f"(d[2]), "+f"(d[3])
        : "r"(a[0]), "r"(a[1]), "r"(a[2]), "r"(a[3]), "r"(b0), "r"(b1));
}

// ---------------- layernorm --------------------------------------------------
template <int WHICH>
__global__ void __launch_bounds__(128) ln_kernel(const float* __restrict__ inp,
                                                 const float* __restrict__ g,
                                                 float* __restrict__ outp)
{
    const float* in  = (WHICH == 0) ? inp  : g_pj;
    float*       out = (WHICH == 0) ? g_xn : outp;
    int row = blockIdx.x;
    int tid = threadIdx.x;
    const float* rptr = in + (size_t)row * DIMC;

    float4 v = reinterpret_cast<const float4*>(rptr)[tid];
    float s  = v.x + v.y + v.z + v.w;
    float ss = v.x * v.x + v.y * v.y + v.z * v.z + v.w * v.w;
    #pragma unroll
    for (int o = 16; o > 0; o >>= 1) {
        s  += __shfl_down_sync(0xffffffffu, s,  o);
        ss += __shfl_down_sync(0xffffffffu, ss, o);
    }
    __shared__ float sb[8];
    int wid = tid >> 5, lane = tid & 31;
    if (lane == 0) { sb[wid] = s; sb[4 + wid] = ss; }
    __syncthreads();
    float S  = sb[0] + sb[1] + sb[2] + sb[3];
    float SS = sb[4] + sb[5] + sb[6] + sb[7];
    float mean = S * (1.0f / DIMC);
    float var  = SS * (1.0f / DIMC) - mean * mean;
    float rstd = rsqrtf(var + 1e-5f);
    float4 gv = reinterpret_cast<const float4*>(g)[tid];
    float4 o4;
    o4.x = (v.x - mean) * rstd * gv.x;
    o4.y = (v.y - mean) * rstd * gv.y;
    o4.z = (v.z - mean) * rstd * gv.z;
    o4.w = (v.w - mean) * rstd * gv.w;
    reinterpret_cast<float4*>(out + (size_t)row * DIMC)[tid] = o4;
}

// ---------------- null kv fill -----------------------------------------------
__global__ void null_fill_kernel(const float* __restrict__ null_kv)
{
    int bh = blockIdx.x;
    int d  = threadIdx.x;
    size_t kidx = (size_t)bh * MK * DH + d;
    bsplit(null_kv[d] * SQSCALE, &g_kh[kidx], &g_kl[kidx]);
    size_t vidx = ((size_t)bh * DH + d) * MKP + 0;
    bsplit(null_kv[DH + d], &g_vth[vidx], &g_vtl[vidx]);
}

// ---------------- weight transpose + split: Wt[n][k] -------------------------
__global__ void __launch_bounds__(256) wsplit_kernel(const float* __restrict__ W,
                                                     __nv_bfloat16* __restrict__ Th,
                                                     __nv_bfloat16* __restrict__ Tl,
                                                     int N)
{
    __shared__ float s[64][65];
    int tid = threadIdx.x;
    int n0 = blockIdx.x * 64;
    int k0 = blockIdx.y * 64;
    #pragma unroll
    for (int i = 0; i < 16; i++) {
        int idx = tid + i * 256;
        int k = idx >> 6, n = idx & 63;
        s[k][n] = W[(size_t)(k0 + k) * N + n0 + n];
    }
    __syncthreads();
    #pragma unroll
    for (int i = 0; i < 16; i++) {
        int idx = tid + i * 256;
        int n = idx >> 6, k = idx & 63;
        size_t o = (size_t)(n0 + n) * 512 + k0 + k;
        bsplit(s[k][n], &Th[o], &Tl[o]);
    }
}

// ---------------- tensor-core projection GEMM --------------------------------
// C(8192 x NC) = A(8192x512, fp32) @ Wt^T (Wt is [n][k] bf16 hi/lo)
// CTA: 64 rows x 64 cols, 4 warps x 16 rows. K chunks of 64.
#define SPIT 72
template <int MODE, int NC>
__global__ void __launch_bounds__(128) proj_mma_kernel(const __nv_bfloat16* __restrict__ Wth,
                                                       const __nv_bfloat16* __restrict__ Wtl,
                                                       const float* __restrict__ Aext)
{
    const float* A = (MODE == 0) ? g_xn : (MODE == 1 ? Aext : g_ao);

    __shared__ __align__(16) __nv_bfloat16 sAh[64 * SPIT];
    __shared__ __align__(16) __nv_bfloat16 sAl[64 * SPIT];
    __shared__ __align__(16) __nv_bfloat16 sBh[64 * SPIT];
    __shared__ __align__(16) __nv_bfloat16 sBl[64 * SPIT];

    int tid  = threadIdx.x;
    int wid  = tid >> 5;
    int lane = tid & 31;
    int g    = lane >> 2;
    int qoff = (lane & 3) << 1;
    int row0 = blockIdx.y * 64;
    int col0 = blockIdx.x * 64;

    float oacc[8][4] = {};

    for (int k0 = 0; k0 < 512; k0 += 64) {
        // stage A chunk (64 rows x 64 k fp32 -> split bf16 hi/lo)
        #pragma unroll
        for (int i = 0; i < 8; i++) {
            int f = tid + i * 128;          // 1024 float4 slots
            int r = f >> 4, c4 = (f & 15) << 2;
            float4 a4 = *(const float4*)(A + (size_t)(row0 + r) * 512 + k0 + c4);
            __nv_bfloat16 h0, h1, h2, h3, l0, l1, l2, l3;
            bsplit(a4.x, &h0, &l0); bsplit(a4.y, &h1, &l1);
            bsplit(a4.z, &h2, &l2); bsplit(a4.w, &h3, &l3);
            uint2 hv, lv;
            hv.x = (uint32_t)__bfloat16_as_ushort(h0) | ((uint32_t)__bfloat16_as_ushort(h1) << 16);
            hv.y = (uint32_t)__bfloat16_as_ushort(h2) | ((uint32_t)__bfloat16_as_ushort(h3) << 16);
            lv.x = (uint32_t)__bfloat16_as_ushort(l0) | ((uint32_t)__bfloat16_as_ushort(l1) << 16);
            lv.y = (uint32_t)__bfloat16_as_ushort(l2) | ((uint32_t)__bfloat16_as_ushort(l3) << 16);
            *(uint2*)(sAh + r * SPIT + c4) = hv;
            *(uint2*)(sAl + r * SPIT + c4) = lv;
        }
        // stage B chunk (64 n-rows x 64 k bf16, straight copy)
        #pragma unroll
        for (int i = 0; i < 4; i++) {
            int f = tid + i * 128;          // 512 uint4 slots
            int r = f >> 3, c = (f & 7) << 3;
            *(uint4*)(sBh + r * SPIT + c) = *(const uint4*)(Wth + (size_t)(col0 + r) * 512 + k0 + c);
            *(uint4*)(sBl + r * SPIT + c) = *(const uint4*)(Wtl + (size_t)(col0 + r) * 512 + k0 + c);
        }
        __syncthreads();

        // A fragments for this warp's 16 rows
        uint32_t afh[4][4], afl[4][4];
        {
            const char* a0h = (const char*)(sAh + (wid * 16 + g) * SPIT);
            const char* a0l = (const char*)(sAl + (wid * 16 + g) * SPIT);
            #pragma unroll
            for (int kt = 0; kt < 4; kt++) {
                int d0 = (kt * 16 + qoff) * 2;
                afh[kt][0] = *(const uint32_t*)(a0h + d0);
                afh[kt][1] = *(const uint32_t*)(a0h + 8 * SPIT * 2 + d0);
                afh[kt][2] = *(const uint32_t*)(a0h + d0 + 16);
                afh[kt][3] = *(const uint32_t*)(a0h + 8 * SPIT * 2 + d0 + 16);
                afl[kt][0] = *(const uint32_t*)(a0l + d0);
                afl[kt][1] = *(const uint32_t*)(a0l + 8 * SPIT * 2 + d0);
                afl[kt][2] = *(const uint32_t*)(a0l + d0 + 16);
                afl[kt][3] = *(const uint32_t*)(a0l + 8 * SPIT * 2 + d0 + 16);
            }
        }

        #pragma unroll
        for (int term = 0; term < 3; term++) {
            const uint32_t (*aa)[4] = (term == 2) ? afl : afh;
            const char* bb = (const char*)((term == 1) ? sBl : sBh);
            #pragma unroll
            for (int kt = 0; kt < 4; kt++) {
                #pragma unroll
                for (int nt = 0; nt < 8; nt++) {
                    const char* bp = bb + (nt * 8 + g) * (SPIT * 2) + (kt * 16 + qoff) * 2;
                    uint32_t b0 = *(const uint32_t*)bp;
                    uint32_t b1 = *(const uint32_t*)(bp + 16);
                    mma16816(oacc[nt], aa[kt], b0, b1);
                }
            }
        }
        __syncthreads();
    }

    // ---- epilogue ----
    #pragma unroll
    for (int nt = 0; nt < 8; nt++) {
        #pragma unroll
        for (int half = 0; half < 2; half++) {
            int row = row0 + wid * 16 + g + half * 8;
            float v0 = oacc[nt][half * 2 + 0];
            float v1 = oacc[nt][half * 2 + 1];
            int c = col0 + nt * 8 + qoff;
            if (MODE == 0) {
                int b = row >> 12, n = row & 4095;
                int h = c >> 6, dd = c & 63;
                size_t idx = (((size_t)(b * HEADS + h)) * NQ + n) * DH + dd;
                bsplit(v0 * SQSCALE, &g_qh[idx],     &g_ql[idx]);
                bsplit(v1 * SQSCALE, &g_qh[idx + 1], &g_ql[idx + 1]);
            } else if (MODE == 1) {
                int b = row >> 12, mr = row & 4095;
                if (c < 512) {
                    int h = c >> 6, dd = c & 63;
                    size_t idx = (((size_t)(b * HEADS + h)) * MK + mr + 1) * DH + dd;
                    bsplit(v0 * SQSCALE, &g_kh[idx],     &g_kl[idx]);
                    bsplit(v1 * SQSCALE, &g_kh[idx + 1], &g_kl[idx + 1]);
                } else {
                    int c2 = c - 512;
                    int h = c2 >> 6, dd = c2 & 63;
                    size_t idx = (((size_t)(b * HEADS + h)) * DH + dd) * MKP + (mr + 1);
                    bsplit(v0, &g_vth[idx],       &g_vtl[idx]);
                    bsplit(v1, &g_vth[idx + MKP], &g_vtl[idx + MKP]);
                }
            } else {
                *(float2*)(g_pj + (size_t)row * 512 + c) = make_float2(v0, v1);
            }
        }
    }
}

// ---------------- FA2-style attention with mma.sync (bf16 split-3) -----------
__global__ void __launch_bounds__(128) attn_mma_kernel(const int* __restrict__ mask)
{
    __shared__ __align__(16) __nv_bfloat16 sKh[64 * SPIT];
    __shared__ __align__(16) __nv_bfloat16 sKl[64 * SPIT];
    __shared__ __align__(16) __nv_bfloat16 sVh[64 * SPIT];   // V^T [dim][key]
    __shared__ __align__(16) __nv_bfloat16 sVl[64 * SPIT];
    __shared__ float msks[64];

    int tid  = threadIdx.x;
    int wid  = tid >> 5;
    int lane = tid & 31;
    int g    = lane >> 2;
    int qoff = (lane & 3) << 1;
    int bh = blockIdx.y;
    int b = bh >> 3, h = bh & 7;
    int n0 = blockIdx.x << 6;

    uint32_t qfh[4][4], qfl[4][4];
    {
        const __nv_bfloat16* q0h = g_qh + ((size_t)bh * NQ + n0 + wid * 16 + g) * DH;
        const __nv_bfloat16* q0l = g_ql + ((size_t)bh * NQ + n0 + wid * 16 + g) * DH;
        #pragma unroll
        for (int kt = 0; kt < 4; kt++) {
            int d0 = kt * 16 + qoff;
            qfh[kt][0] = *(const uint32_t*)(q0h + d0);
            qfh[kt][1] = *(const uint32_t*)(q0h + 8 * DH + d0);
            qfh[kt][2] = *(const uint32_t*)(q0h + d0 + 8);
            qfh[kt][3] = *(const uint32_t*)(q0h + 8 * DH + d0 + 8);
            qfl[kt][0] = *(const uint32_t*)(q0l + d0);
            qfl[kt][1] = *(const uint32_t*)(q0l + 8 * DH + d0);
            qfl[kt][2] = *(const uint32_t*)(q0l + d0 + 8);
            qfl[kt][3] = *(const uint32_t*)(q0l + 8 * DH + d0 + 8);
        }
    }

    float oacc[8][4] = {};
    float sum0 = 0.0f, sum1 = 0.0f;

    for (int c0 = 0; c0 < MK; c0 += 64) {
        __syncthreads();

        if (wid < 2) {
            const __nv_bfloat16* gk = (wid == 0) ? g_kh : g_kl;
            __nv_bfloat16* sK = (wid == 0) ? sKh : sKl;
            #pragma unroll
            for (int i = 0; i < 2; i++) {
                int r = (lane << 1) | i;
                uint4* dst = (uint4*)(sK + r * SPIT);
                int j = c0 + r;
                if (j < MK) {
                    const uint4* src = (const uint4*)(gk + ((size_t)bh * MK + j) * DH);
                    #pragma unroll
                    for (int w = 0; w < 8; w++) dst[w] = src[w];
                } else {
                    uint4 z = {0u, 0u, 0u, 0u};
                    #pragma unroll
                    for (int w = 0; w < 8; w++) dst[w] = z;
                }
            }
        } else {
            const __nv_bfloat16* gv = (wid == 2) ? g_vth : g_vtl;
            __nv_bfloat16* sV = (wid == 2) ? sVh : sVl;
            #pragma unroll
            for (int i = 0; i < 2; i++) {
                int dd = (lane << 1) | i;
                const __nv_bfloat16* src = gv + ((size_t)bh * DH + dd) * MKP + c0;
                if (c0 + 64 <= MK) {
                    uint4* dst = (uint4*)(sV + dd * SPIT);
                    #pragma unroll
                    for (int w = 0; w < 8; w++) dst[w] = ((const uint4*)src)[w];
                } else {
                    __nv_bfloat16* db = sV + dd * SPIT;
                    for (int e = 0; e < 64; e++)
                        db[e] = (c0 + e < MK) ? src[e] : __float2bfloat16(0.0f);
                }
            }
        }
        if (tid < 64) {
            int j = c0 + tid;
            float ok;
            if (j == 0)      ok = 1.0f;
            else if (j < MK) ok = mask[b * NCTX + (j - 1)] ? 1.0f : 0.0f;
            else             ok = 0.0f;
            msks[tid] = ok;
        }
        __syncthreads();

        float sacc[8][4] = {};
        #pragma unroll
        for (int term = 0; term < 3; term++) {
            const uint32_t (*qa)[4] = (term == 2) ? qfl : qfh;
            const char* kb = (const char*)((term == 1) ? sKl : sKh);
            #pragma unroll
            for (int kt = 0; kt < 4; kt++) {
                #pragma unroll
                for (int nt = 0; nt < 8; nt++) {
                    const char* bp = kb + (nt * 8 + g) * (SPIT * 2) + (kt * 16 + qoff) * 2;
                    uint32_t b0 = *(const uint32_t*)bp;
                    uint32_t b1 = *(const uint32_t*)(bp + 16);
                    mma16816(sacc[nt], qa[kt], b0, b1);
                }
            }
        }

        uint32_t pfh[4][4], pfl[4][4];
        #pragma unroll
        for (int nt = 0; nt < 8; nt++) {
            float2 mv = *(const float2*)(msks + nt * 8 + qoff);
            float p0 = mv.x * __expf(fminf(sacc[nt][0], 30.0f));
            float p1 = mv.y * __expf(fminf(sacc[nt][1], 30.0f));
            float p2 = mv.x * __expf(fminf(sacc[nt][2], 30.0f));
            float p3 = mv.y * __expf(fminf(sacc[nt][3], 30.0f));
            sum0 += p0 + p1;
            sum1 += p2 + p3;
            float h0 = __bfloat162float(__float2bfloat16(p0));
            float h1 = __bfloat162float(__float2bfloat16(p1));
            float h2 = __bfloat162float(__float2bfloat16(p2));
            float h3 = __bfloat162float(__float2bfloat16(p3));
            int kt = nt >> 1, hf = (nt & 1) << 1;
            pfh[kt][hf + 0] = pack_bf16x2(h0, h1);
            pfh[kt][hf + 1] = pack_bf16x2(h2, h3);
            pfl[kt][hf + 0] = pack_bf16x2(p0 - h0, p1 - h1);
            pfl[kt][hf + 1] = pack_bf16x2(p2 - h2, p3 - h3);
        }

        #pragma unroll
        for (int term = 0; term < 3; term++) {
            const uint32_t (*pa)[4] = (term == 2) ? pfl : pfh;
            const char* vb = (const char*)((term == 1) ? sVl : sVh);
            #pragma unroll
            for (int kt = 0; kt < 4; kt++) {
                #pragma unroll
                for (int nt = 0; nt < 8; nt++) {
                    const char* bp = vb + (nt * 8 + g) * (SPIT * 2) + (kt * 16 + qoff) * 2;
                    uint32_t b0 = *(const uint32_t*)bp;
                    uint32_t b1 = *(const uint32_t*)(bp + 16);
                    mma16816(oacc[nt], pa[kt], b0, b1);
                }
            }
        }
    }

    sum0 += __shfl_xor_sync(0xffffffffu, sum0, 1);
    sum0 += __shfl_xor_sync(0xffffffffu, sum0, 2);
    sum1 += __shfl_xor_sync(0xffffffffu, sum1, 1);
    sum1 += __shfl_xor_sync(0xffffffffu, sum1, 2);
    float inv0 = 1.0f / sum0;
    float inv1 = 1.0f / sum1;

    float* orow0 = g_ao + ((size_t)b * NQ + n0 + wid * 16 + g) * INNER + h * DH;
    float* orow1 = orow0 + 8 * INNER;
    #pragma unroll
    for (int nt = 0; nt < 8; nt++) {
        float2 v0 = make_float2(oacc[nt][0] * inv0, oacc[nt][1] * inv0);
        float2 v1 = make_float2(oacc[nt][2] * inv1, oacc[nt][3] * inv1);
        *(float2*)(orow0 + nt * 8 + qoff) = v0;
        *(float2*)(orow1 + nt * 8 + qoff) = v1;
    }
}

// ---------------- launch ------------------------------------------------------
extern "C" void kernel_launch(void* const* d_in, const int* in_sizes, int n_in,
                              void* d_out, int out_size)
{
    const float* x       = (const float*)d_in[0];
    const float* context = (const float*)d_in[1];
    const int*   mask    = (const int*)  d_in[2];
    const float* g_x     = (const float*)d_in[3];
    const float* null_kv = (const float*)d_in[4];
    const float* Wq      = (const float*)d_in[5];
    const float* Wkv     = (const float*)d_in[6];
    const float* Wo      = (const float*)d_in[7];
    const float* g_outp  = (const float*)d_in[8];
    float* out = (float*)d_out;
    (void)in_sizes; (void)n_in; (void)out_size;

    __nv_bfloat16 *wqh, *wql, *wkvh, *wkvl, *woh, *wol;
    cudaGetSymbolAddress((void**)&wqh,  g_wqh);
    cudaGetSymbolAddress((void**)&wql,  g_wql);
    cudaGetSymbolAddress((void**)&wkvh, g_wkvh);
    cudaGetSymbolAddress((void**)&wkvl, g_wkvl);
    cudaGetSymbolAddress((void**)&woh,  g_woh);
    cudaGetSymbolAddress((void**)&wol,  g_wol);

    // weight prep (transpose + split)
    wsplit_kernel<<<dim3(8, 8),  256>>>(Wq,  wqh,  wql,  512);
    wsplit_kernel<<<dim3(16, 8), 256>>>(Wkv, wkvh, wkvl, 1024);
    wsplit_kernel<<<dim3(8, 8),  256>>>(Wo,  woh,  wol,  512);

    ln_kernel<0><<<BATCH * NQ, 128>>>(x, g_x, nullptr);
    proj_mma_kernel<0, 512><<<dim3(8, 128), 128>>>(wqh, wql, nullptr);
    proj_mma_kernel<1, 1024><<<dim3(16, 128), 128>>>(wkvh, wkvl, context);
    null_fill_kernel<<<BATCH * HEADS, DH>>>(null_kv);

    attn_mma_kernel<<<dim3(NQ / 64, BATCH * HEADS), 128>>>(mask);

    proj_mma_kernel<2, 512><<<dim3(8, 128), 128>>>(woh, wol, nullptr);
    ln_kernel<1><<<BATCH * NQ, 128>>>(nullptr, g_outp, out);
}

// round 7
// speedup vs baseline: 3.2624x; 1.1440x over previous
#include <cuda_runtime.h>
#include <cuda_bf16.h>
#include <math.h>
#include <stdint.h>

// ---------------- problem constants ----------------
#define BATCH   2
#define NQ      4096
#define NCTX    4096
#define DIMC    512
#define HEADS   8
#define DH      64
#define INNER   512
#define MK      4097         // keys incl. null
#define MKP     4104         // padded stride for V^T (16B-aligned rows)
#define SQSCALE 0.35355339059327373f   // sqrt(64^-0.5)
#define SPIT    72           // smem pitch (bf16 elems) = 144B

// ---------------- scratch ----------------------------------------------------
__device__ float g_xn[(size_t)BATCH * NQ * DIMC];
__device__ float g_ao[(size_t)BATCH * NQ * INNER];
__device__ float g_pj[(size_t)BATCH * NQ * DIMC];

__device__ __nv_bfloat16 g_qh[(size_t)BATCH * HEADS * NQ * DH];
__device__ __nv_bfloat16 g_ql[(size_t)BATCH * HEADS * NQ * DH];
__device__ __nv_bfloat16 g_kh[(size_t)BATCH * HEADS * MK * DH];
__device__ __nv_bfloat16 g_kl[(size_t)BATCH * HEADS * MK * DH];
__device__ __nv_bfloat16 g_vth[(size_t)BATCH * HEADS * DH * MKP];  // [bh][d][key]
__device__ __nv_bfloat16 g_vtl[(size_t)BATCH * HEADS * DH * MKP];

// transposed/split weights: Wt[n][k], k = 512
__device__ __nv_bfloat16 g_wqh[512 * 512],  g_wql[512 * 512];
__device__ __nv_bfloat16 g_wkvh[1024 * 512], g_wkvl[1024 * 512];
__device__ __nv_bfloat16 g_woh[512 * 512],  g_wol[512 * 512];

// ---------------- helpers -----------------------------------------------------
__device__ __forceinline__ void bsplit(float v, __nv_bfloat16* hi, __nv_bfloat16* lo) {
    __nv_bfloat16 h = __float2bfloat16(v);
    *hi = h;
    *lo = __float2bfloat16(v - __bfloat162float(h));
}
__device__ __forceinline__ uint32_t pack_bf16x2(float lo_elem, float hi_elem) {
    uint32_t r;
    asm("cvt.rn.bf16x2.f32 %0, %1, %2;" : "=r"(r) : "f"(hi_elem), "f"(lo_elem));
    return r;
}
__device__ __forceinline__ void mma16816(float* d, const uint32_t* a, uint32_t b0, uint32_t b1) {
    asm volatile("mma.sync.aligned.m16n8k16.row.col.f32.bf16.bf16.f32 "
        "{%0,%1,%2,%3}, {%4,%5,%6,%7}, {%8,%9}, {%0,%1,%2,%3};"
        : "+f"(d[0]), "+f"(d[1]), "+f"(d[2]), "+f"(d[3])
        : "r"(a[0]), "r"(a[1]), "r"(a[2]), "r"(a[3]), "r"(b0), "r"(b1));
}
__device__ __forceinline__ void ldsm_x4(uint32_t* r, uint32_t addr) {
    asm volatile("ldmatrix.sync.aligned.m8n8.x4.shared.b16 {%0,%1,%2,%3}, [%4];"
        : "=r"(r[0]), "=r"(r[1]), "=r"(r[2]), "=r"(r[3]) : "r"(addr));
}

// ---------------- layernorm --------------------------------------------------
template <int WHICH>
__global__ void __launch_bounds__(128) ln_kernel(const float* __restrict__ inp,
                                                 const float* __restrict__ g,
                                                 float* __restrict__ outp)
{
    const float* in  = (WHICH == 0) ? inp  : g_pj;
    float*       out = (WHICH == 0) ? g_xn : outp;
    int row = blockIdx.x;
    int tid = threadIdx.x;
    const float* rptr = in + (size_t)row * DIMC;

    float4 v = reinterpret_cast<const float4*>(rptr)[tid];
    float s  = v.x + v.y + v.z + v.w;
    float ss = v.x * v.x + v.y * v.y + v.z * v.z + v.w * v.w;
    #pragma unroll
    for (int o = 16; o > 0; o >>= 1) {
        s  += __shfl_down_sync(0xffffffffu, s,  o);
        ss += __shfl_down_sync(0xffffffffu, ss, o);
    }
    __shared__ float sb[8];
    int wid = tid >> 5, lane = tid & 31;
    if (lane == 0) { sb[wid] = s; sb[4 + wid] = ss; }
    __syncthreads();
    float S  = sb[0] + sb[1] + sb[2] + sb[3];
    float SS = sb[4] + sb[5] + sb[6] + sb[7];
    float mean = S * (1.0f / DIMC);
    float var  = SS * (1.0f / DIMC) - mean * mean;
    float rstd = rsqrtf(var + 1e-5f);
    float4 gv = reinterpret_cast<const float4*>(g)[tid];
    float4 o4;
    o4.x = (v.x - mean) * rstd * gv.x;
    o4.y = (v.y - mean) * rstd * gv.y;
    o4.z = (v.z - mean) * rstd * gv.z;
    o4.w = (v.w - mean) * rstd * gv.w;
    reinterpret_cast<float4*>(out + (size_t)row * DIMC)[tid] = o4;
}

// ---------------- null kv fill -----------------------------------------------
__global__ void null_fill_kernel(const float* __restrict__ null_kv)
{
    int bh = blockIdx.x;
    int d  = threadIdx.x;
    size_t kidx = (size_t)bh * MK * DH + d;
    bsplit(null_kv[d] * SQSCALE, &g_kh[kidx], &g_kl[kidx]);
    size_t vidx = ((size_t)bh * DH + d) * MKP + 0;
    bsplit(null_kv[DH + d], &g_vth[vidx], &g_vtl[vidx]);
}

// ---------------- weight transpose + split: Wt[n][k] -------------------------
__global__ void __launch_bounds__(256) wsplit_kernel(const float* __restrict__ W,
                                                     __nv_bfloat16* __restrict__ Th,
                                                     __nv_bfloat16* __restrict__ Tl,
                                                     int N)
{
    __shared__ float s[64][65];
    int tid = threadIdx.x;
    int n0 = blockIdx.x * 64;
    int k0 = blockIdx.y * 64;
    #pragma unroll
    for (int i = 0; i < 16; i++) {
        int idx = tid + i * 256;
        int k = idx >> 6, n = idx & 63;
        s[k][n] = W[(size_t)(k0 + k) * N + n0 + n];
    }
    __syncthreads();
    #pragma unroll
    for (int i = 0; i < 16; i++) {
        int idx = tid + i * 256;
        int n = idx >> 6, k = idx & 63;
        size_t o = (size_t)(n0 + n) * 512 + k0 + k;
        bsplit(s[k][n], &Th[o], &Tl[o]);
    }
}

// ---------------- tensor-core projection GEMM (ldmatrix) ---------------------
template <int MODE, int NC>
__global__ void __launch_bounds__(128) proj_mma_kernel(const __nv_bfloat16* __restrict__ Wth,
                                                       const __nv_bfloat16* __restrict__ Wtl,
                                                       const float* __restrict__ Aext)
{
    const float* A = (MODE == 0) ? g_xn : (MODE == 1 ? Aext : g_ao);

    __shared__ __align__(16) __nv_bfloat16 sAh[64 * SPIT];
    __shared__ __align__(16) __nv_bfloat16 sAl[64 * SPIT];
    __shared__ __align__(16) __nv_bfloat16 sBh[64 * SPIT];
    __shared__ __align__(16) __nv_bfloat16 sBl[64 * SPIT];

    int tid  = threadIdx.x;
    int wid  = tid >> 5;
    int lane = tid & 31;
    int g    = lane >> 2;
    int qoff = (lane & 3) << 1;
    int row0 = blockIdx.y * 64;
    int col0 = blockIdx.x * 64;

    uint32_t uAh = (uint32_t)__cvta_generic_to_shared(sAh);
    uint32_t uAl = (uint32_t)__cvta_generic_to_shared(sAl);
    uint32_t uBh = (uint32_t)__cvta_generic_to_shared(sBh);
    uint32_t uBl = (uint32_t)__cvta_generic_to_shared(sBl);

    int lm = lane >> 3, li = lane & 7;
    // A x4: m0=rows(+0,k0) m1=rows(+8,k0) m2=rows(+0,k8) m3=rows(+8,k8)
    uint32_t aoff = (uint32_t)(((wid * 16 + (lm & 1) * 8 + li) * SPIT + (lm >> 1) * 8) * 2);
    // B x4: m0=(n0,k0) m1=(n0,k8) m2=(n8,k0) m3=(n8,k8)
    uint32_t boff = (uint32_t)((((lm >> 1) * 8 + li) * SPIT + (lm & 1) * 8) * 2);

    float oacc[8][4] = {};

    for (int k0 = 0; k0 < 512; k0 += 64) {
        #pragma unroll
        for (int i = 0; i < 8; i++) {
            int f = tid + i * 128;
            int r = f >> 4, c4 = (f & 15) << 2;
            float4 a4 = *(const float4*)(A + (size_t)(row0 + r) * 512 + k0 + c4);
            __nv_bfloat16 h0, h1, h2, h3, l0, l1, l2, l3;
            bsplit(a4.x, &h0, &l0); bsplit(a4.y, &h1, &l1);
            bsplit(a4.z, &h2, &l2); bsplit(a4.w, &h3, &l3);
            uint2 hv, lv;
            hv.x = (uint32_t)__bfloat16_as_ushort(h0) | ((uint32_t)__bfloat16_as_ushort(h1) << 16);
            hv.y = (uint32_t)__bfloat16_as_ushort(h2) | ((uint32_t)__bfloat16_as_ushort(h3) << 16);
            lv.x = (uint32_t)__bfloat16_as_ushort(l0) | ((uint32_t)__bfloat16_as_ushort(l1) << 16);
            lv.y = (uint32_t)__bfloat16_as_ushort(l2) | ((uint32_t)__bfloat16_as_ushort(l3) << 16);
            *(uint2*)(sAh + r * SPIT + c4) = hv;
            *(uint2*)(sAl + r * SPIT + c4) = lv;
        }
        #pragma unroll
        for (int i = 0; i < 4; i++) {
            int f = tid + i * 128;
            int r = f >> 3, c = (f & 7) << 3;
            *(uint4*)(sBh + r * SPIT + c) = *(const uint4*)(Wth + (size_t)(col0 + r) * 512 + k0 + c);
            *(uint4*)(sBl + r * SPIT + c) = *(const uint4*)(Wtl + (size_t)(col0 + r) * 512 + k0 + c);
        }
        __syncthreads();

        uint32_t afh[4][4], afl[4][4];
        #pragma unroll
        for (int kt = 0; kt < 4; kt++) {
            ldsm_x4(afh[kt], uAh + (uint32_t)(kt * 32) + aoff);
            ldsm_x4(afl[kt], uAl + (uint32_t)(kt * 32) + aoff);
        }

        #pragma unroll
        for (int kt = 0; kt < 4; kt++) {
            #pragma unroll
            for (int ntp = 0; ntp < 4; ntp++) {
                uint32_t off = (uint32_t)(ntp * 16 * SPIT * 2 + kt * 32) + boff;
                uint32_t bhf[4], blf[4];
                ldsm_x4(bhf, uBh + off);
                ldsm_x4(blf, uBl + off);
                mma16816(oacc[2 * ntp],     afh[kt], bhf[0], bhf[1]);
                mma16816(oacc[2 * ntp + 1], afh[kt], bhf[2], bhf[3]);
                mma16816(oacc[2 * ntp],     afl[kt], bhf[0], bhf[1]);
                mma16816(oacc[2 * ntp + 1], afl[kt], bhf[2], bhf[3]);
                mma16816(oacc[2 * ntp],     afh[kt], blf[0], blf[1]);
                mma16816(oacc[2 * ntp + 1], afh[kt], blf[2], blf[3]);
            }
        }
        __syncthreads();
    }

    #pragma unroll
    for (int nt = 0; nt < 8; nt++) {
        #pragma unroll
        for (int half = 0; half < 2; half++) {
            int row = row0 + wid * 16 + g + half * 8;
            float v0 = oacc[nt][half * 2 + 0];
            float v1 = oacc[nt][half * 2 + 1];
            int c = col0 + nt * 8 + qoff;
            if (MODE == 0) {
                int b = row >> 12, n = row & 4095;
                int h = c >> 6, dd = c & 63;
                size_t idx = (((size_t)(b * HEADS + h)) * NQ + n) * DH + dd;
                bsplit(v0 * SQSCALE, &g_qh[idx],     &g_ql[idx]);
                bsplit(v1 * SQSCALE, &g_qh[idx + 1], &g_ql[idx + 1]);
            } else if (MODE == 1) {
                int b = row >> 12, mr = row & 4095;
                if (c < 512) {
                    int h = c >> 6, dd = c & 63;
                    size_t idx = (((size_t)(b * HEADS + h)) * MK + mr + 1) * DH + dd;
                    bsplit(v0 * SQSCALE, &g_kh[idx],     &g_kl[idx]);
                    bsplit(v1 * SQSCALE, &g_kh[idx + 1], &g_kl[idx + 1]);
                } else {
                    int c2 = c - 512;
                    int h = c2 >> 6, dd = c2 & 63;
                    size_t idx = (((size_t)(b * HEADS + h)) * DH + dd) * MKP + (mr + 1);
                    bsplit(v0, &g_vth[idx],       &g_vtl[idx]);
                    bsplit(v1, &g_vth[idx + MKP], &g_vtl[idx + MKP]);
                }
            } else {
                *(float2*)(g_pj + (size_t)row * 512 + c) = make_float2(v0, v1);
            }
        }
    }
}

// ---------------- FA2 attention: R4 staging + ldmatrix compute ----------------
__global__ void __launch_bounds__(128) attn_mma_kernel(const int* __restrict__ mask)
{
    __shared__ __align__(16) __nv_bfloat16 sKh[64 * SPIT];
    __shared__ __align__(16) __nv_bfloat16 sKl[64 * SPIT];
    __shared__ __align__(16) __nv_bfloat16 sVh[64 * SPIT];   // V^T [dim][key]
    __shared__ __align__(16) __nv_bfloat16 sVl[64 * SPIT];
    __shared__ float msks[64];

    int tid  = threadIdx.x;
    int wid  = tid >> 5;
    int lane = tid & 31;
    int g    = lane >> 2;
    int qoff = (lane & 3) << 1;
    int bh = blockIdx.y;
    int b = bh >> 3, h = bh & 7;
    int n0 = blockIdx.x << 6;

    uint32_t uKh = (uint32_t)__cvta_generic_to_shared(sKh);
    uint32_t uKl = (uint32_t)__cvta_generic_to_shared(sKl);
    uint32_t uVh = (uint32_t)__cvta_generic_to_shared(sVh);
    uint32_t uVl = (uint32_t)__cvta_generic_to_shared(sVl);
    int lm = lane >> 3, li = lane & 7;
    uint32_t boff = (uint32_t)((((lm >> 1) * 8 + li) * SPIT + (lm & 1) * 8) * 2);

    // ---- Q fragments (hi/lo) from gmem (R4 proven) ----
    uint32_t qfh[4][4], qfl[4][4];
    {
        const __nv_bfloat16* q0h = g_qh + ((size_t)bh * NQ + n0 + wid * 16 + g) * DH;
        const __nv_bfloat16* q0l = g_ql + ((size_t)bh * NQ + n0 + wid * 16 + g) * DH;
        #pragma unroll
        for (int kt = 0; kt < 4; kt++) {
            int d0 = kt * 16 + qoff;
            qfh[kt][0] = *(const uint32_t*)(q0h + d0);
            qfh[kt][1] = *(const uint32_t*)(q0h + 8 * DH + d0);
            qfh[kt][2] = *(const uint32_t*)(q0h + d0 + 8);
            qfh[kt][3] = *(const uint32_t*)(q0h + 8 * DH + d0 + 8);
            qfl[kt][0] = *(const uint32_t*)(q0l + d0);
            qfl[kt][1] = *(const uint32_t*)(q0l + 8 * DH + d0);
            qfl[kt][2] = *(const uint32_t*)(q0l + d0 + 8);
            qfl[kt][3] = *(const uint32_t*)(q0l + 8 * DH + d0 + 8);
        }
    }

    float oacc[8][4] = {};
    float sum0 = 0.0f, sum1 = 0.0f;

    for (int c0 = 0; c0 < MK; c0 += 64) {
        __syncthreads();

        // ---- stage K rows / V^T rows (R4 verbatim) ----
        if (wid < 2) {
            const __nv_bfloat16* gk = (wid == 0) ? g_kh : g_kl;
            __nv_bfloat16* sK = (wid == 0) ? sKh : sKl;
            #pragma unroll
            for (int i = 0; i < 2; i++) {
                int r = (lane << 1) | i;
                uint4* dst = (uint4*)(sK + r * SPIT);
                int j = c0 + r;
                if (j < MK) {
                    const uint4* src = (const uint4*)(gk + ((size_t)bh * MK + j) * DH);
                    #pragma unroll
                    for (int w = 0; w < 8; w++) dst[w] = src[w];
                } else {
                    uint4 z = {0u, 0u, 0u, 0u};
                    #pragma unroll
                    for (int w = 0; w < 8; w++) dst[w] = z;
                }
            }
        } else {
            const __nv_bfloat16* gv = (wid == 2) ? g_vth : g_vtl;
            __nv_bfloat16* sV = (wid == 2) ? sVh : sVl;
            #pragma unroll
            for (int i = 0; i < 2; i++) {
                int dd = (lane << 1) | i;
                const __nv_bfloat16* src = gv + ((size_t)bh * DH + dd) * MKP + c0;
                if (c0 + 64 <= MK) {
                    uint4* dst = (uint4*)(sV + dd * SPIT);
                    #pragma unroll
                    for (int w = 0; w < 8; w++) dst[w] = ((const uint4*)src)[w];
                } else {
                    __nv_bfloat16* db = sV + dd * SPIT;
                    for (int e = 0; e < 64; e++)
                        db[e] = (c0 + e < MK) ? src[e] : __float2bfloat16(0.0f);
                }
            }
        }
        if (tid < 64) {
            int j = c0 + tid;
            float ok;
            if (j == 0)      ok = 1.0f;
            else if (j < MK) ok = mask[b * NCTX + (j - 1)] ? 1.0f : 0.0f;
            else             ok = 0.0f;
            msks[tid] = ok;
        }
        __syncthreads();

        // ---- S = Q K^T : ldmatrix B, shared across 3 split terms ----
        float sacc[8][4] = {};
        #pragma unroll
        for (int kt = 0; kt < 4; kt++) {
            #pragma unroll
            for (int ntp = 0; ntp < 4; ntp++) {
                uint32_t off = (uint32_t)(ntp * 16 * SPIT * 2 + kt * 32) + boff;
                uint32_t bhf[4], blf[4];
                ldsm_x4(bhf, uKh + off);
                ldsm_x4(blf, uKl + off);
                mma16816(sacc[2 * ntp],     qfh[kt], bhf[0], bhf[1]);
                mma16816(sacc[2 * ntp + 1], qfh[kt], bhf[2], bhf[3]);
                mma16816(sacc[2 * ntp],     qfl[kt], bhf[0], bhf[1]);
                mma16816(sacc[2 * ntp + 1], qfl[kt], bhf[2], bhf[3]);
                mma16816(sacc[2 * ntp],     qfh[kt], blf[0], blf[1]);
                mma16816(sacc[2 * ntp + 1], qfh[kt], blf[2], blf[3]);
            }
        }

        // ---- softmax (R4 verbatim) ----
        uint32_t pfh[4][4], pfl[4][4];
        #pragma unroll
        for (int nt = 0; nt < 8; nt++) {
            float2 mv = *(const float2*)(msks + nt * 8 + qoff);
            float p0 = mv.x * __expf(fminf(sacc[nt][0], 30.0f));
            float p1 = mv.y * __expf(fminf(sacc[nt][1], 30.0f));
            float p2 = mv.x * __expf(fminf(sacc[nt][2], 30.0f));
            float p3 = mv.y * __expf(fminf(sacc[nt][3], 30.0f));
            sum0 += p0 + p1;
            sum1 += p2 + p3;
            float h0 = __bfloat162float(__float2bfloat16(p0));
            float h1 = __bfloat162float(__float2bfloat16(p1));
            float h2 = __bfloat162float(__float2bfloat16(p2));
            float h3 = __bfloat162float(__float2bfloat16(p3));
            int kt = nt >> 1, hf = (nt & 1) << 1;
            pfh[kt][hf + 0] = pack_bf16x2(h0, h1);
            pfh[kt][hf + 1] = pack_bf16x2(h2, h3);
            pfl[kt][hf + 0] = pack_bf16x2(p0 - h0, p1 - h1);
            pfl[kt][hf + 1] = pack_bf16x2(p2 - h2, p3 - h3);
        }

        // ---- O += P V : ldmatrix B, shared across 3 split terms ----
        #pragma unroll
        for (int kt = 0; kt < 4; kt++) {
            #pragma unroll
            for (int ntp = 0; ntp < 4; ntp++) {
                uint32_t off = (uint32_t)(ntp * 16 * SPIT * 2 + kt * 32) + boff;
                uint32_t vhf[4], vlf[4];
                ldsm_x4(vhf, uVh + off);
                ldsm_x4(vlf, uVl + off);
                mma16816(oacc[2 * ntp],     pfh[kt], vhf[0], vhf[1]);
                mma16816(oacc[2 * ntp + 1], pfh[kt], vhf[2], vhf[3]);
                mma16816(oacc[2 * ntp],     pfl[kt], vhf[0], vhf[1]);
                mma16816(oacc[2 * ntp + 1], pfl[kt], vhf[2], vhf[3]);
                mma16816(oacc[2 * ntp],     pfh[kt], vlf[0], vlf[1]);
                mma16816(oacc[2 * ntp + 1], pfh[kt], vlf[2], vlf[3]);
            }
        }
    }

    sum0 += __shfl_xor_sync(0xffffffffu, sum0, 1);
    sum0 += __shfl_xor_sync(0xffffffffu, sum0, 2);
    sum1 += __shfl_xor_sync(0xffffffffu, sum1, 1);
    sum1 += __shfl_xor_sync(0xffffffffu, sum1, 2);
    float inv0 = 1.0f / sum0;
    float inv1 = 1.0f / sum1;

    float* orow0 = g_ao + ((size_t)b * NQ + n0 + wid * 16 + g) * INNER + h * DH;
    float* orow1 = orow0 + 8 * INNER;
    #pragma unroll
    for (int nt = 0; nt < 8; nt++) {
        float2 v0 = make_float2(oacc[nt][0] * inv0, oacc[nt][1] * inv0);
        float2 v1 = make_float2(oacc[nt][2] * inv1, oacc[nt][3] * inv1);
        *(float2*)(orow0 + nt * 8 + qoff) = v0;
        *(float2*)(orow1 + nt * 8 + qoff) = v1;
    }
}

// ---------------- launch ------------------------------------------------------
extern "C" void kernel_launch(void* const* d_in, const int* in_sizes, int n_in,
                              void* d_out, int out_size)
{
    const float* x       = (const float*)d_in[0];
    const float* context = (const float*)d_in[1];
    const int*   mask    = (const int*)  d_in[2];
    const float* g_x     = (const float*)d_in[3];
    const float* null_kv = (const float*)d_in[4];
    const float* Wq      = (const float*)d_in[5];
    const float* Wkv     = (const float*)d_in[6];
    const float* Wo      = (const float*)d_in[7];
    const float* g_outp  = (const float*)d_in[8];
    float* out = (float*)d_out;
    (void)in_sizes; (void)n_in; (void)out_size;

    __nv_bfloat16 *wqh, *wql, *wkvh, *wkvl, *woh, *wol;
    cudaGetSymbolAddress((void**)&wqh,  g_wqh);
    cudaGetSymbolAddress((void**)&wql,  g_wql);
    cudaGetSymbolAddress((void**)&wkvh, g_wkvh);
    cudaGetSymbolAddress((void**)&wkvl, g_wkvl);
    cudaGetSymbolAddress((void**)&woh,  g_woh);
    cudaGetSymbolAddress((void**)&wol,  g_wol);

    wsplit_kernel<<<dim3(8, 8),  256>>>(Wq,  wqh,  wql,  512);
    wsplit_kernel<<<dim3(16, 8), 256>>>(Wkv, wkvh, wkvl, 1024);
    wsplit_kernel<<<dim3(8, 8),  256>>>(Wo,  woh,  wol,  512);

    ln_kernel<0><<<BATCH * NQ, 128>>>(x, g_x, nullptr);
    proj_mma_kernel<0, 512><<<dim3(8, 128), 128>>>(wqh, wql, nullptr);
    proj_mma_kernel<1, 1024><<<dim3(16, 128), 128>>>(wkvh, wkvl, context);
    null_fill_kernel<<<BATCH * HEADS, DH>>>(null_kv);

    attn_mma_kernel<<<dim3(NQ / 64, BATCH * HEADS), 128>>>(mask);

    proj_mma_kernel<2, 512><<<dim3(8, 128), 128>>>(woh, wol, nullptr);
    ln_kernel<1><<<BATCH * NQ, 128>>>(nullptr, g_outp, out);
}

// round 8
// speedup vs baseline: 4.4129x; 1.3526x over previous
#include <cuda_runtime.h>
#include <cuda_bf16.h>
#include <math.h>
#include <stdint.h>

// ---------------- problem constants ----------------
#define BATCH   2
#define NQ      4096
#define NCTX    4096
#define DIMC    512
#define HEADS   8
#define DH      64
#define INNER   512
#define MK      4097         // keys incl. null
#define MKP     4160         // padded V^T stride (covers 65*64 tail, zeros in pad)
#define SQSCALE 0.35355339059327373f   // sqrt(64^-0.5)
#define SPIT    72           // smem pitch (bf16 elems) = 144B

// ---------------- scratch ----------------------------------------------------
__device__ float g_xn[(size_t)BATCH * NQ * DIMC];
__device__ float g_ao[(size_t)BATCH * NQ * INNER];
__device__ float g_pj[(size_t)BATCH * NQ * DIMC];

__device__ __nv_bfloat16 g_qh[(size_t)BATCH * HEADS * NQ * DH];
__device__ __nv_bfloat16 g_ql[(size_t)BATCH * HEADS * NQ * DH];
__device__ __nv_bfloat16 g_kh[(size_t)BATCH * HEADS * MK * DH];
__device__ __nv_bfloat16 g_kl[(size_t)BATCH * HEADS * MK * DH];
__device__ __nv_bfloat16 g_vth[(size_t)BATCH * HEADS * DH * MKP];  // [bh][d][key]
__device__ __nv_bfloat16 g_vtl[(size_t)BATCH * HEADS * DH * MKP];

// transposed/split weights: Wt[n][k], k = 512
__device__ __nv_bfloat16 g_wqh[512 * 512],  g_wql[512 * 512];
__device__ __nv_bfloat16 g_wkvh[1024 * 512], g_wkvl[1024 * 512];
__device__ __nv_bfloat16 g_woh[512 * 512],  g_wol[512 * 512];

// ---------------- helpers -----------------------------------------------------
__device__ __forceinline__ void bsplit(float v, __nv_bfloat16* hi, __nv_bfloat16* lo) {
    __nv_bfloat16 h = __float2bfloat16(v);
    *hi = h;
    *lo = __float2bfloat16(v - __bfloat162float(h));
}
__device__ __forceinline__ uint32_t pack_bf16x2(float lo_elem, float hi_elem) {
    uint32_t r;
    asm("cvt.rn.bf16x2.f32 %0, %1, %2;" : "=r"(r) : "f"(hi_elem), "f"(lo_elem));
    return r;
}
__device__ __forceinline__ void mma16816(float* d, const uint32_t* a, uint32_t b0, uint32_t b1) {
    asm volatile("mma.sync.aligned.m16n8k16.row.col.f32.bf16.bf16.f32 "
        "{%0,%1,%2,%3}, {%4,%5,%6,%7}, {%8,%9}, {%0,%1,%2,%3};"
        : "+f"(d[0]), "+f"(d[1]), "+f"(d[2]), "+f"(d[3])
        : "r"(a[0]), "r"(a[1]), "r"(a[2]), "r"(a[3]), "r"(b0), "r"(b1));
}
__device__ __forceinline__ void ldsm_x4(uint32_t* r, uint32_t addr) {
    asm volatile("ldmatrix.sync.aligned.m8n8.x4.shared.b16 {%0,%1,%2,%3}, [%4];"
        : "=r"(r[0]), "=r"(r[1]), "=r"(r[2]), "=r"(r[3]) : "r"(addr));
}
__device__ __forceinline__ void cp16(uint32_t dst, const void* src) {
    asm volatile("cp.async.cg.shared.global [%0], [%1], 16;"
        :: "r"(dst), "l"(src) : "memory");
}
__device__ __forceinline__ void cp16z(uint32_t dst, const void* src, int ok) {
    int sz = ok ? 16 : 0;
    asm volatile("cp.async.cg.shared.global [%0], [%1], 16, %2;"
        :: "r"(dst), "l"(src), "r"(sz) : "memory");
}
#define CP_COMMIT() asm volatile("cp.async.commit_group;" ::: "memory")
#define CP_WAIT0()  asm volatile("cp.async.wait_group 0;" ::: "memory")

// ---------------- layernorm --------------------------------------------------
template <int WHICH>
__global__ void __launch_bounds__(128) ln_kernel(const float* __restrict__ inp,
                                                 const float* __restrict__ g,
                                                 float* __restrict__ outp)
{
    const float* in  = (WHICH == 0) ? inp  : g_pj;
    float*       out = (WHICH == 0) ? g_xn : outp;
    int row = blockIdx.x;
    int tid = threadIdx.x;
    const float* rptr = in + (size_t)row * DIMC;

    float4 v = reinterpret_cast<const float4*>(rptr)[tid];
    float s  = v.x + v.y + v.z + v.w;
    float ss = v.x * v.x + v.y * v.y + v.z * v.z + v.w * v.w;
    #pragma unroll
    for (int o = 16; o > 0; o >>= 1) {
        s  += __shfl_down_sync(0xffffffffu, s,  o);
        ss += __shfl_down_sync(0xffffffffu, ss, o);
    }
    __shared__ float sb[8];
    int wid = tid >> 5, lane = tid & 31;
    if (lane == 0) { sb[wid] = s; sb[4 + wid] = ss; }
    __syncthreads();
    float S  = sb[0] + sb[1] + sb[2] + sb[3];
    float SS = sb[4] + sb[5] + sb[6] + sb[7];
    float mean = S * (1.0f / DIMC);
    float var  = SS * (1.0f / DIMC) - mean * mean;
    float rstd = rsqrtf(var + 1e-5f);
    float4 gv = reinterpret_cast<const float4*>(g)[tid];
    float4 o4;
    o4.x = (v.x - mean) * rstd * gv.x;
    o4.y = (v.y - mean) * rstd * gv.y;
    o4.z = (v.z - mean) * rstd * gv.z;
    o4.w = (v.w - mean) * rstd * gv.w;
    reinterpret_cast<float4*>(out + (size_t)row * DIMC)[tid] = o4;
}

// ---------------- null kv fill -----------------------------------------------
__global__ void null_fill_kernel(const float* __restrict__ null_kv)
{
    int bh = blockIdx.x;
    int d  = threadIdx.x;
    size_t kidx = (size_t)bh * MK * DH + d;
    bsplit(null_kv[d] * SQSCALE, &g_kh[kidx], &g_kl[kidx]);
    size_t vidx = ((size_t)bh * DH + d) * MKP + 0;
    bsplit(null_kv[DH + d], &g_vth[vidx], &g_vtl[vidx]);
}

// ---------------- weight transpose + split: Wt[n][k] -------------------------
__global__ void __launch_bounds__(256) wsplit_kernel(const float* __restrict__ W,
                                                     __nv_bfloat16* __restrict__ Th,
                                                     __nv_bfloat16* __restrict__ Tl,
                                                     int N)
{
    __shared__ float s[64][65];
    int tid = threadIdx.x;
    int n0 = blockIdx.x * 64;
    int k0 = blockIdx.y * 64;
    #pragma unroll
    for (int i = 0; i < 16; i++) {
        int idx = tid + i * 256;
        int k = idx >> 6, n = idx & 63;
        s[k][n] = W[(size_t)(k0 + k) * N + n0 + n];
    }
    __syncthreads();
    #pragma unroll
    for (int i = 0; i < 16; i++) {
        int idx = tid + i * 256;
        int n = idx >> 6, k = idx & 63;
        size_t o = (size_t)(n0 + n) * 512 + k0 + k;
        bsplit(s[k][n], &Th[o], &Tl[o]);
    }
}

// ---------------- tensor-core projection GEMM (ldmatrix, R7-proven) ----------
template <int MODE, int NC>
__global__ void __launch_bounds__(128) proj_mma_kernel(const __nv_bfloat16* __restrict__ Wth,
                                                       const __nv_bfloat16* __restrict__ Wtl,
                                                       const float* __restrict__ Aext)
{
    const float* A = (MODE == 0) ? g_xn : (MODE == 1 ? Aext : g_ao);

    __shared__ __align__(16) __nv_bfloat16 sAh[64 * SPIT];
    __shared__ __align__(16) __nv_bfloat16 sAl[64 * SPIT];
    __shared__ __align__(16) __nv_bfloat16 sBh[64 * SPIT];
    __shared__ __align__(16) __nv_bfloat16 sBl[64 * SPIT];

    int tid  = threadIdx.x;
    int wid  = tid >> 5;
    int lane = tid & 31;
    int g    = lane >> 2;
    int qoff = (lane & 3) << 1;
    int row0 = blockIdx.y * 64;
    int col0 = blockIdx.x * 64;

    uint32_t uAh = (uint32_t)__cvta_generic_to_shared(sAh);
    uint32_t uAl = (uint32_t)__cvta_generic_to_shared(sAl);
    uint32_t uBh = (uint32_t)__cvta_generic_to_shared(sBh);
    uint32_t uBl = (uint32_t)__cvta_generic_to_shared(sBl);

    int lm = lane >> 3, li = lane & 7;
    uint32_t aoff = (uint32_t)(((wid * 16 + (lm & 1) * 8 + li) * SPIT + (lm >> 1) * 8) * 2);
    uint32_t boff = (uint32_t)((((lm >> 1) * 8 + li) * SPIT + (lm & 1) * 8) * 2);

    float oacc[8][4] = {};

    for (int k0 = 0; k0 < 512; k0 += 64) {
        #pragma unroll
        for (int i = 0; i < 8; i++) {
            int f = tid + i * 128;
            int r = f >> 4, c4 = (f & 15) << 2;
            float4 a4 = *(const float4*)(A + (size_t)(row0 + r) * 512 + k0 + c4);
            __nv_bfloat16 h0, h1, h2, h3, l0, l1, l2, l3;
            bsplit(a4.x, &h0, &l0); bsplit(a4.y, &h1, &l1);
            bsplit(a4.z, &h2, &l2); bsplit(a4.w, &h3, &l3);
            uint2 hv, lv;
            hv.x = (uint32_t)__bfloat16_as_ushort(h0) | ((uint32_t)__bfloat16_as_ushort(h1) << 16);
            hv.y = (uint32_t)__bfloat16_as_ushort(h2) | ((uint32_t)__bfloat16_as_ushort(h3) << 16);
            lv.x = (uint32_t)__bfloat16_as_ushort(l0) | ((uint32_t)__bfloat16_as_ushort(l1) << 16);
            lv.y = (uint32_t)__bfloat16_as_ushort(l2) | ((uint32_t)__bfloat16_as_ushort(l3) << 16);
            *(uint2*)(sAh + r * SPIT + c4) = hv;
            *(uint2*)(sAl + r * SPIT + c4) = lv;
        }
        #pragma unroll
        for (int i = 0; i < 4; i++) {
            int f = tid + i * 128;
            int r = f >> 3, c = (f & 7) << 3;
            *(uint4*)(sBh + r * SPIT + c) = *(const uint4*)(Wth + (size_t)(col0 + r) * 512 + k0 + c);
            *(uint4*)(sBl + r * SPIT + c) = *(const uint4*)(Wtl + (size_t)(col0 + r) * 512 + k0 + c);
        }
        __syncthreads();

        uint32_t afh[4][4], afl[4][4];
        #pragma unroll
        for (int kt = 0; kt < 4; kt++) {
            ldsm_x4(afh[kt], uAh + (uint32_t)(kt * 32) + aoff);
            ldsm_x4(afl[kt], uAl + (uint32_t)(kt * 32) + aoff);
        }

        #pragma unroll
        for (int kt = 0; kt < 4; kt++) {
            #pragma unroll
            for (int ntp = 0; ntp < 4; ntp++) {
                uint32_t off = (uint32_t)(ntp * 16 * SPIT * 2 + kt * 32) + boff;
                uint32_t bhf[4], blf[4];
                ldsm_x4(bhf, uBh + off);
                ldsm_x4(blf, uBl + off);
                mma16816(oacc[2 * ntp],     afh[kt], bhf[0], bhf[1]);
                mma16816(oacc[2 * ntp + 1], afh[kt], bhf[2], bhf[3]);
                mma16816(oacc[2 * ntp],     afl[kt], bhf[0], bhf[1]);
                mma16816(oacc[2 * ntp + 1], afl[kt], bhf[2], bhf[3]);
                mma16816(oacc[2 * ntp],     afh[kt], blf[0], blf[1]);
                mma16816(oacc[2 * ntp + 1], afh[kt], blf[2], blf[3]);
            }
        }
        __syncthreads();
    }

    #pragma unroll
    for (int nt = 0; nt < 8; nt++) {
        #pragma unroll
        for (int half = 0; half < 2; half++) {
            int row = row0 + wid * 16 + g + half * 8;
            float v0 = oacc[nt][half * 2 + 0];
            float v1 = oacc[nt][half * 2 + 1];
            int c = col0 + nt * 8 + qoff;
            if (MODE == 0) {
                int b = row >> 12, n = row & 4095;
                int h = c >> 6, dd = c & 63;
                size_t idx = (((size_t)(b * HEADS + h)) * NQ + n) * DH + dd;
                bsplit(v0 * SQSCALE, &g_qh[idx],     &g_ql[idx]);
                bsplit(v1 * SQSCALE, &g_qh[idx + 1], &g_ql[idx + 1]);
            } else if (MODE == 1) {
                int b = row >> 12, mr = row & 4095;
                if (c < 512) {
                    int h = c >> 6, dd = c & 63;
                    size_t idx = (((size_t)(b * HEADS + h)) * MK + mr + 1) * DH + dd;
                    bsplit(v0 * SQSCALE, &g_kh[idx],     &g_kl[idx]);
                    bsplit(v1 * SQSCALE, &g_kh[idx + 1], &g_kl[idx + 1]);
                } else {
                    int c2 = c - 512;
                    int h = c2 >> 6, dd = c2 & 63;
                    size_t idx = (((size_t)(b * HEADS + h)) * DH + dd) * MKP + (mr + 1);
                    bsplit(v0, &g_vth[idx],       &g_vtl[idx]);
                    bsplit(v1, &g_vth[idx + MKP], &g_vtl[idx + MKP]);
                }
            } else {
                *(float2*)(g_pj + (size_t)row * 512 + c) = make_float2(v0, v1);
            }
        }
    }
}

// ---------------- FA2 attention: ldmatrix + cp.async double-buffer ------------
// buffer layout per stage: Kh(0) Kl(9216) Vh(18432) Vl(27648); BUFSZ=36864, x2.
#define BUFSZ   36864
#define OFF_BM  73728
#define ATTN_SMEM 74272
#define NCH     65

__global__ void __launch_bounds__(128) attn_mma_kernel(const int* __restrict__ mask)
{
    extern __shared__ char smc[];
    const int tid  = threadIdx.x;
    const int wid  = tid >> 5;
    const int lane = tid & 31;
    const int g    = lane >> 2;
    const int qoff = (lane & 3) << 1;
    const int bh = blockIdx.y;
    const int b = bh >> 3, h = bh & 7;
    const int n0 = blockIdx.x << 6;

    uint32_t sbase = (uint32_t)__cvta_generic_to_shared(smc);
    uint32_t* bmap = (uint32_t*)(smc + OFF_BM);

    // one-time mask bitmap (keys 0..4159) — STRIDED: blockDim is 128 < 130!
    for (int w = tid; w < 130; w += 128) {
        uint32_t wv = 0;
        int jb = w * 32;
        #pragma unroll 8
        for (int i = 0; i < 32; i++) {
            int j = jb + i;
            int ok = (j == 0) ? 1 : ((j < MK) ? (mask[b * NCTX + j - 1] != 0) : 0);
            wv |= (uint32_t)ok << i;
        }
        bmap[w] = wv;
    }

    // Q fragments (hi/lo) from gmem
    uint32_t qfh[4][4], qfl[4][4];
    {
        const __nv_bfloat16* q0h = g_qh + ((size_t)bh * NQ + n0 + wid * 16 + g) * DH;
        const __nv_bfloat16* q0l = g_ql + ((size_t)bh * NQ + n0 + wid * 16 + g) * DH;
        #pragma unroll
        for (int kt = 0; kt < 4; kt++) {
            int d0 = kt * 16 + qoff;
            qfh[kt][0] = *(const uint32_t*)(q0h + d0);
            qfh[kt][1] = *(const uint32_t*)(q0h + 8 * DH + d0);
            qfh[kt][2] = *(const uint32_t*)(q0h + d0 + 8);
            qfh[kt][3] = *(const uint32_t*)(q0h + 8 * DH + d0 + 8);
            qfl[kt][0] = *(const uint32_t*)(q0l + d0);
            qfl[kt][1] = *(const uint32_t*)(q0l + 8 * DH + d0);
            qfl[kt][2] = *(const uint32_t*)(q0l + d0 + 8);
            qfl[kt][3] = *(const uint32_t*)(q0l + 8 * DH + d0 + 8);
        }
    }

    const int lm = lane >> 3, li = lane & 7;
    const uint32_t boff = (uint32_t)((((lm >> 1) * 8 + li) * SPIT + (lm & 1) * 8) * 2);

    // cp.async staging of one 64-key chunk into buffer `buf`
    auto stage = [&](int c0s, int buf) {
        #pragma unroll
        for (int i = 0; i < 16; i++) {
            int idx = tid + i * 128;          // 0..2047
            int part = idx >> 9;              // 0=Kh 1=Kl 2=Vh 3=Vl
            int rem = idx & 511;
            int r = rem >> 3, cc = (rem & 7) << 3;
            uint32_t dst = sbase + (uint32_t)(buf * BUFSZ + part * 9216 + (r * SPIT + cc) * 2);
            if (part < 2) {
                int j = c0s + r;
                const __nv_bfloat16* ks = ((part & 1) ? g_kl : g_kh)
                    + ((size_t)bh * MK + min(j, MK - 1)) * DH + cc;
                cp16z(dst, ks, j < MK);       // zero-fill beyond MK
            } else {
                const __nv_bfloat16* vs = ((part & 1) ? g_vtl : g_vth)
                    + ((size_t)bh * DH + r) * MKP + c0s + cc;   // pad cols are zeros
                cp16(dst, vs);
            }
        }
    };

    stage(0, 0);
    CP_COMMIT();

    float oacc[8][4] = {};
    float sum0 = 0.0f, sum1 = 0.0f;

    for (int ch = 0; ch < NCH; ch++) {
        int c0 = ch << 6;
        CP_WAIT0();
        __syncthreads();
        if (ch + 1 < NCH) { stage((ch + 1) << 6, (ch + 1) & 1); CP_COMMIT(); }

        uint32_t uKh = sbase + (uint32_t)((ch & 1) * BUFSZ);
        uint32_t uKl = uKh + 9216;
        uint32_t uVh = uKh + 18432;
        uint32_t uVl = uKh + 27648;

        // ---- S = Q K^T : ldmatrix B shared across 3 split terms ----
        float sacc[8][4] = {};
        #pragma unroll
        for (int kt = 0; kt < 4; kt++) {
            #pragma unroll
            for (int ntp = 0; ntp < 4; ntp++) {
                uint32_t off = (uint32_t)(ntp * 16 * SPIT * 2 + kt * 32) + boff;
                uint32_t bhf[4], blf[4];
                ldsm_x4(bhf, uKh + off);
                ldsm_x4(blf, uKl + off);
                mma16816(sacc[2 * ntp],     qfh[kt], bhf[0], bhf[1]);
                mma16816(sacc[2 * ntp + 1], qfh[kt], bhf[2], bhf[3]);
                mma16816(sacc[2 * ntp],     qfl[kt], bhf[0], bhf[1]);
                mma16816(sacc[2 * ntp + 1], qfl[kt], bhf[2], bhf[3]);
                mma16816(sacc[2 * ntp],     qfh[kt], blf[0], blf[1]);
                mma16816(sacc[2 * ntp + 1], qfh[kt], blf[2], blf[3]);
            }
        }

        // ---- softmax (bitmap mask, no max-subtract) + pack P ----
        uint32_t pfh[4][4], pfl[4][4];
        #pragma unroll
        for (int nt = 0; nt < 8; nt++) {
            int j0 = c0 + nt * 8 + qoff;
            uint32_t wb = bmap[j0 >> 5];
            int bi = j0 & 31;
            float m0 = (float)((wb >> bi) & 1u);
            float m1 = (float)((wb >> (bi + 1)) & 1u);
            float p0 = m0 * __expf(fminf(sacc[nt][0], 30.0f));
            float p1 = m1 * __expf(fminf(sacc[nt][1], 30.0f));
            float p2 = m0 * __expf(fminf(sacc[nt][2], 30.0f));
            float p3 = m1 * __expf(fminf(sacc[nt][3], 30.0f));
            sum0 += p0 + p1;
            sum1 += p2 + p3;
            float h0 = __bfloat162float(__float2bfloat16(p0));
            float h1 = __bfloat162float(__float2bfloat16(p1));
            float h2 = __bfloat162float(__float2bfloat16(p2));
            float h3 = __bfloat162float(__float2bfloat16(p3));
            int kt = nt >> 1, hf = (nt & 1) << 1;
            pfh[kt][hf + 0] = pack_bf16x2(h0, h1);
            pfh[kt][hf + 1] = pack_bf16x2(h2, h3);
            pfl[kt][hf + 0] = pack_bf16x2(p0 - h0, p1 - h1);
            pfl[kt][hf + 1] = pack_bf16x2(p2 - h2, p3 - h3);
        }

        // ---- O += P V : ldmatrix B shared across 3 split terms ----
        #pragma unroll
        for (int kt = 0; kt < 4; kt++) {
            #pragma unroll
            for (int ntp = 0; ntp < 4; ntp++) {
                uint32_t off = (uint32_t)(ntp * 16 * SPIT * 2 + kt * 32) + boff;
                uint32_t vhf[4], vlf[4];
                ldsm_x4(vhf, uVh + off);
                ldsm_x4(vlf, uVl + off);
                mma16816(oacc[2 * ntp],     pfh[kt], vhf[0], vhf[1]);
                mma16816(oacc[2 * ntp + 1], pfh[kt], vhf[2], vhf[3]);
                mma16816(oacc[2 * ntp],     pfl[kt], vhf[0], vhf[1]);
                mma16816(oacc[2 * ntp + 1], pfl[kt], vhf[2], vhf[3]);
                mma16816(oacc[2 * ntp],     pfh[kt], vlf[0], vlf[1]);
                mma16816(oacc[2 * ntp + 1], pfh[kt], vlf[2], vlf[3]);
            }
        }
    }

    sum0 += __shfl_xor_sync(0xffffffffu, sum0, 1);
    sum0 += __shfl_xor_sync(0xffffffffu, sum0, 2);
    sum1 += __shfl_xor_sync(0xffffffffu, sum1, 1);
    sum1 += __shfl_xor_sync(0xffffffffu, sum1, 2);
    float inv0 = 1.0f / sum0;
    float inv1 = 1.0f / sum1;

    float* orow0 = g_ao + ((size_t)b * NQ + n0 + wid * 16 + g) * INNER + h * DH;
    float* orow1 = orow0 + 8 * INNER;
    #pragma unroll
    for (int nt = 0; nt < 8; nt++) {
        float2 v0 = make_float2(oacc[nt][0] * inv0, oacc[nt][1] * inv0);
        float2 v1 = make_float2(oacc[nt][2] * inv1, oacc[nt][3] * inv1);
        *(float2*)(orow0 + nt * 8 + qoff) = v0;
        *(float2*)(orow1 + nt * 8 + qoff) = v1;
    }
}

// ---------------- launch ------------------------------------------------------
extern "C" void kernel_launch(void* const* d_in, const int* in_sizes, int n_in,
                              void* d_out, int out_size)
{
    const float* x       = (const float*)d_in[0];
    const float* context = (const float*)d_in[1];
    const int*   mask    = (const int*)  d_in[2];
    const float* g_x     = (const float*)d_in[3];
    const float* null_kv = (const float*)d_in[4];
    const float* Wq      = (const float*)d_in[5];
    const float* Wkv     = (const float*)d_in[6];
    const float* Wo      = (const float*)d_in[7];
    const float* g_outp  = (const float*)d_in[8];
    float* out = (float*)d_out;
    (void)in_sizes; (void)n_in; (void)out_size;

    __nv_bfloat16 *wqh, *wql, *wkvh, *wkvl, *woh, *wol;
    cudaGetSymbolAddress((void**)&wqh,  g_wqh);
    cudaGetSymbolAddress((void**)&wql,  g_wql);
    cudaGetSymbolAddress((void**)&wkvh, g_wkvh);
    cudaGetSymbolAddress((void**)&wkvl, g_wkvl);
    cudaGetSymbolAddress((void**)&woh,  g_woh);
    cudaGetSymbolAddress((void**)&wol,  g_wol);

    wsplit_kernel<<<dim3(8, 8),  256>>>(Wq,  wqh,  wql,  512);
    wsplit_kernel<<<dim3(16, 8), 256>>>(Wkv, wkvh, wkvl, 1024);
    wsplit_kernel<<<dim3(8, 8),  256>>>(Wo,  woh,  wol,  512);

    ln_kernel<0><<<BATCH * NQ, 128>>>(x, g_x, nullptr);
    proj_mma_kernel<0, 512><<<dim3(8, 128), 128>>>(wqh, wql, nullptr);
    proj_mma_kernel<1, 1024><<<dim3(16, 128), 128>>>(wkvh, wkvl, context);
    null_fill_kernel<<<BATCH * HEADS, DH>>>(null_kv);

    cudaFuncSetAttribute(attn_mma_kernel, cudaFuncAttributeMaxDynamicSharedMemorySize, ATTN_SMEM);
    attn_mma_kernel<<<dim3(NQ / 64, BATCH * HEADS), 128, ATTN_SMEM>>>(mask);

    proj_mma_kernel<2, 512><<<dim3(8, 128), 128>>>(woh, wol, nullptr);
    ln_kernel<1><<<BATCH * NQ, 128>>>(nullptr, g_outp, out);
}